// round 12
// baseline (speedup 1.0000x reference)
#include <cuda_runtime.h>
#include <cuda_bf16.h>
#include <cstdint>
#include <math.h>

#define SEQ    4096
#define DMODEL 1024
#define NHEAD  16
#define DHEAD  64

typedef __nv_bfloat16 bf16;

__device__ __forceinline__ uint32_t smem_u32(const void* p) {
    uint32_t a;
    asm("{ .reg .u64 t; cvta.to.shared.u64 t, %1; cvt.u32.u64 %0, t; }" : "=r"(a) : "l"(p));
    return a;
}
__device__ __forceinline__ void ldsm_x4(uint32_t* r, uint32_t addr) {
    asm volatile("ldmatrix.sync.aligned.m8n8.x4.shared.b16 {%0,%1,%2,%3}, [%4];"
        : "=r"(r[0]), "=r"(r[1]), "=r"(r[2]), "=r"(r[3]) : "r"(addr));
}
__device__ __forceinline__ void mma_bf16(float* c, const uint32_t* a, const uint32_t* b) {
    asm volatile(
        "mma.sync.aligned.m16n8k16.row.col.f32.bf16.bf16.f32 "
        "{%0,%1,%2,%3}, {%4,%5,%6,%7}, {%8,%9}, {%0,%1,%2,%3};"
        : "+f"(c[0]), "+f"(c[1]), "+f"(c[2]), "+f"(c[3])
        : "r"(a[0]), "r"(a[1]), "r"(a[2]), "r"(a[3]), "r"(b[0]), "r"(b[1]));
}
__device__ __forceinline__ float ex2f(float x) {
    float y; asm("ex2.approx.f32 %0,%1;" : "=f"(y) : "f"(x)); return y;
}
__device__ __forceinline__ uint32_t packbf2(float lo, float hi) {
    uint32_t d; asm("cvt.rn.bf16x2.f32 %0,%1,%2;" : "=r"(d) : "f"(hi), "f"(lo)); return d;
}
__device__ __forceinline__ float bf16rt(float x) {
    return __bfloat162float(__float2bfloat16(x));
}

#define CP_ASYNC16(dst, src) \
    asm volatile("cp.async.cg.shared.global [%0],[%1],16;" :: "r"(dst), "l"(src))
#define CP_COMMIT()  asm volatile("cp.async.commit_group;")
#define CP_WAIT(n)   asm volatile("cp.async.wait_group %0;" :: "n"(n))

#define TSCL 0.1803368801f   /* 0.125 * log2(e), folded into W_Q */

// ========================= scratch (__device__ globals) =====================
__device__ bf16 g_qh[(size_t)NHEAD * SEQ * DHEAD], g_ql[(size_t)NHEAD * SEQ * DHEAD];
__device__ bf16 g_kh[(size_t)NHEAD * SEQ * DHEAD], g_kl[(size_t)NHEAD * SEQ * DHEAD];
__device__ bf16 g_vth[(size_t)NHEAD * SEQ * DHEAD], g_vtl[(size_t)NHEAD * SEQ * DHEAD];
__device__ bf16 g_zh[(size_t)SEQ * DMODEL], g_zl[(size_t)SEQ * DMODEL];
__device__ bf16 g_xh[(size_t)SEQ * DMODEL], g_xl[(size_t)SEQ * DMODEL];
__device__ bf16 g_wqh[DMODEL * DMODEL], g_wql[DMODEL * DMODEL];
__device__ bf16 g_wkh[DMODEL * DMODEL], g_wkl[DMODEL * DMODEL];
__device__ bf16 g_wvh[DMODEL * DMODEL], g_wvl[DMODEL * DMODEL];
__device__ bf16 g_woh[DMODEL * DMODEL], g_wol[DMODEL * DMODEL];

// ============================ split kernels =================================
__global__ __launch_bounds__(256) void split_kernel(
    const float* __restrict__ in, bf16* __restrict__ hi,
    bf16* __restrict__ lo, int n4, float scale)
{
    int i = blockIdx.x * 256 + threadIdx.x;
    if (i >= n4) return;
    float4 v = ((const float4*)in)[i];
    v.x *= scale; v.y *= scale; v.z *= scale; v.w *= scale;
    uint32_t* H = (uint32_t*)hi;
    uint32_t* L = (uint32_t*)lo;
    H[2 * i]     = packbf2(v.x, v.y);
    H[2 * i + 1] = packbf2(v.z, v.w);
    L[2 * i]     = packbf2(v.x - bf16rt(v.x), v.y - bf16rt(v.y));
    L[2 * i + 1] = packbf2(v.z - bf16rt(v.z), v.w - bf16rt(v.w));
}

// 4 weight tensors in one launch; y selects {WQ(TSCL), WK, WV, WO}
__global__ __launch_bounds__(256) void split4_kernel(
    const float* __restrict__ w0, const float* __restrict__ w1,
    const float* __restrict__ w2, const float* __restrict__ w3,
    bf16* __restrict__ h0, bf16* __restrict__ l0,
    bf16* __restrict__ h1, bf16* __restrict__ l1,
    bf16* __restrict__ h2, bf16* __restrict__ l2,
    bf16* __restrict__ h3, bf16* __restrict__ l3, int n4)
{
    int i = blockIdx.x * 256 + threadIdx.x;
    if (i >= n4) return;
    const int z = blockIdx.y;
    const float* in = (z == 0) ? w0 : (z == 1) ? w1 : (z == 2) ? w2 : w3;
    bf16* hi = (z == 0) ? h0 : (z == 1) ? h1 : (z == 2) ? h2 : h3;
    bf16* lo = (z == 0) ? l0 : (z == 1) ? l1 : (z == 2) ? l2 : l3;
    const float scale = (z == 0) ? TSCL : 1.0f;
    float4 v = ((const float4*)in)[i];
    v.x *= scale; v.y *= scale; v.z *= scale; v.w *= scale;
    uint32_t* H = (uint32_t*)hi;
    uint32_t* L = (uint32_t*)lo;
    H[2 * i]     = packbf2(v.x, v.y);
    H[2 * i + 1] = packbf2(v.z, v.w);
    L[2 * i]     = packbf2(v.x - bf16rt(v.x), v.y - bf16rt(v.y));
    L[2 * i + 1] = packbf2(v.z - bf16rt(v.z), v.w - bf16rt(v.w));
}

// =============== shared GEMM mainloop (3-term split, cp.async) ==============
#define GSTR 40
#define GBUF (128 * GSTR)
#define NITER 96

__device__ __forceinline__ void gemm_core(
    const bf16* __restrict__ Ah, const bf16* __restrict__ Al,
    const bf16* __restrict__ Bh, const bf16* __restrict__ Bl,
    int m0, int n0, bf16* As, bf16* Bs, float acc[2][8][4])
{
    const int tid  = threadIdx.x;
    const int warp = tid >> 5, lane = tid & 31;
    const int wm = (warp & 3) * 32;
    const int wn = (warp >> 2) * 64;

    const uint32_t as_base = smem_u32(As);
    const uint32_t bs_base = smem_u32(Bs);
    const uint32_t a_addr0 = as_base + ((wm + (lane & 15)) * GSTR + (lane >> 4) * 8) * 2;
    const uint32_t b_addr0 = bs_base +
        ((wn + (lane & 7) + ((lane >> 4) * 8)) * GSTR + (((lane >> 3) & 1) * 8)) * 2;

    const int crow0 = tid >> 2, ccol = (tid & 3) * 8;
    const int crow1 = (tid + 256) >> 2;

    const bf16* Aps[3]; const bf16* Bps[3];
    Aps[0] = Ah; Bps[0] = Bh;  Aps[1] = Ah; Bps[1] = Bl;  Aps[2] = Al; Bps[2] = Bh;

#pragma unroll
    for (int i = 0; i < 2; ++i)
#pragma unroll
        for (int j = 0; j < 8; ++j)
#pragma unroll
            for (int t = 0; t < 4; ++t) acc[i][j][t] = 0.0f;

    {
        const bf16* Ap = Aps[0]; const bf16* Bp = Bps[0];
        CP_ASYNC16(as_base + (crow0 * GSTR + ccol) * 2, Ap + (size_t)(m0 + crow0) * DMODEL + ccol);
        CP_ASYNC16(as_base + (crow1 * GSTR + ccol) * 2, Ap + (size_t)(m0 + crow1) * DMODEL + ccol);
        CP_ASYNC16(bs_base + (crow0 * GSTR + ccol) * 2, Bp + (size_t)(n0 + crow0) * DMODEL + ccol);
        CP_ASYNC16(bs_base + (crow1 * GSTR + ccol) * 2, Bp + (size_t)(n0 + crow1) * DMODEL + ccol);
        CP_COMMIT();
    }

#pragma unroll 1
    for (int c = 0; c < NITER; ++c) {
        const int buf = c & 1;
        if (c + 1 < NITER) {
            const int cn = c + 1;
            const bf16* Ap = Aps[cn >> 5];
            const bf16* Bp = Bps[cn >> 5];
            const int k0 = (cn & 31) * 32;
            const uint32_t ao = as_base + (cn & 1) * GBUF * 2;
            const uint32_t bo = bs_base + (cn & 1) * GBUF * 2;
            CP_ASYNC16(ao + (crow0 * GSTR + ccol) * 2, Ap + (size_t)(m0 + crow0) * DMODEL + k0 + ccol);
            CP_ASYNC16(ao + (crow1 * GSTR + ccol) * 2, Ap + (size_t)(m0 + crow1) * DMODEL + k0 + ccol);
            CP_ASYNC16(bo + (crow0 * GSTR + ccol) * 2, Bp + (size_t)(n0 + crow0) * DMODEL + k0 + ccol);
            CP_ASYNC16(bo + (crow1 * GSTR + ccol) * 2, Bp + (size_t)(n0 + crow1) * DMODEL + k0 + ccol);
            CP_COMMIT();
            CP_WAIT(1);
        } else {
            CP_WAIT(0);
        }
        __syncthreads();

        const uint32_t abuf = buf * GBUF * 2;
#pragma unroll
        for (int kk = 0; kk < 2; ++kk) {
            uint32_t a[2][4], b[8][2];
#pragma unroll
            for (int mt = 0; mt < 2; ++mt)
                ldsm_x4(a[mt], a_addr0 + abuf + (mt * 16 * GSTR + kk * 16) * 2);
#pragma unroll
            for (int j = 0; j < 4; ++j) {
                uint32_t r[4];
                ldsm_x4(r, b_addr0 + abuf + (j * 16 * GSTR + kk * 16) * 2);
                b[j * 2][0] = r[0]; b[j * 2][1] = r[1];
                b[j * 2 + 1][0] = r[2]; b[j * 2 + 1][1] = r[3];
            }
#pragma unroll
            for (int mt = 0; mt < 2; ++mt)
#pragma unroll
                for (int nt = 0; nt < 8; ++nt)
                    mma_bf16(acc[mt][nt], a[mt], b[nt]);
        }
        __syncthreads();
    }
}

// ---- fused QKV projection: z selects {Q->mode1, K->mode1, V->mode2} ----
__global__ __launch_bounds__(256) void gemm_qkv(
    const bf16* __restrict__ xh, const bf16* __restrict__ xl,
    const bf16* __restrict__ wqh, const bf16* __restrict__ wql,
    const bf16* __restrict__ wkh, const bf16* __restrict__ wkl,
    const bf16* __restrict__ wvh, const bf16* __restrict__ wvl,
    bf16* __restrict__ qh, bf16* __restrict__ ql,
    bf16* __restrict__ kh, bf16* __restrict__ kl,
    bf16* __restrict__ vth, bf16* __restrict__ vtl)
{
    __shared__ bf16 As[2][GBUF];
    __shared__ bf16 Bs[2][GBUF];
    const int sel = blockIdx.z;
    const bf16* Bh = (sel == 0) ? wqh : (sel == 1) ? wkh : wvh;
    const bf16* Bl = (sel == 0) ? wql : (sel == 1) ? wkl : wvl;
    bf16* Ch = (sel == 0) ? qh : (sel == 1) ? kh : vth;
    bf16* Cl = (sel == 0) ? ql : (sel == 1) ? kl : vtl;

    const int m0 = blockIdx.x * 128;
    const int n0 = blockIdx.y * 128;
    float acc[2][8][4];
    gemm_core(xh, xl, Bh, Bl, m0, n0, As[0], Bs[0], acc);

    const int warp = threadIdx.x >> 5, lane = threadIdx.x & 31;
    const int wm = (warp & 3) * 32, wn = (warp >> 2) * 64;
#pragma unroll
    for (int mt = 0; mt < 2; ++mt) {
#pragma unroll
        for (int nt = 0; nt < 8; ++nt) {
            int m = m0 + wm + mt * 16 + (lane >> 2);
            int n = n0 + wn + nt * 8 + 2 * (lane & 3);
            float c0 = acc[mt][nt][0], c1 = acc[mt][nt][1];
            float c2 = acc[mt][nt][2], c3 = acc[mt][nt][3];
            if (sel != 2) {
                size_t i0 = ((size_t)(n >> 6) * SEQ + m) * 64 + (n & 63);
                *(uint32_t*)(Ch + i0) = packbf2(c0, c1);
                *(uint32_t*)(Cl + i0) = packbf2(c0 - bf16rt(c0), c1 - bf16rt(c1));
                *(uint32_t*)(Ch + i0 + 8 * 64) = packbf2(c2, c3);
                *(uint32_t*)(Cl + i0 + 8 * 64) = packbf2(c2 - bf16rt(c2), c3 - bf16rt(c3));
            } else {
                size_t b0 = ((size_t)(n >> 6) * 64 + (n & 63)) * SEQ;
                Ch[b0 + m] = __float2bfloat16(c0);
                Cl[b0 + m] = __float2bfloat16(c0 - bf16rt(c0));
                Ch[b0 + m + 8] = __float2bfloat16(c2);
                Cl[b0 + m + 8] = __float2bfloat16(c2 - bf16rt(c2));
                Ch[b0 + SEQ + m] = __float2bfloat16(c1);
                Cl[b0 + SEQ + m] = __float2bfloat16(c1 - bf16rt(c1));
                Ch[b0 + SEQ + m + 8] = __float2bfloat16(c3);
                Cl[b0 + SEQ + m + 8] = __float2bfloat16(c3 - bf16rt(c3));
            }
        }
    }
}

// ---- output projection (fp32 C) ----
__global__ __launch_bounds__(256) void gemm_out(
    const bf16* __restrict__ Ah, const bf16* __restrict__ Al,
    const bf16* __restrict__ Bh, const bf16* __restrict__ Bl,
    float* __restrict__ C)
{
    __shared__ bf16 As[2][GBUF];
    __shared__ bf16 Bs[2][GBUF];
    const int m0 = blockIdx.x * 128;
    const int n0 = blockIdx.y * 128;
    float acc[2][8][4];
    gemm_core(Ah, Al, Bh, Bl, m0, n0, As[0], Bs[0], acc);

    const int warp = threadIdx.x >> 5, lane = threadIdx.x & 31;
    const int wm = (warp & 3) * 32, wn = (warp >> 2) * 64;
#pragma unroll
    for (int mt = 0; mt < 2; ++mt) {
#pragma unroll
        for (int nt = 0; nt < 8; ++nt) {
            int m = m0 + wm + mt * 16 + (lane >> 2);
            int n = n0 + wn + nt * 8 + 2 * (lane & 3);
            *(float2*)(C + (size_t)m * DMODEL + n) =
                make_float2(acc[mt][nt][0], acc[mt][nt][1]);
            *(float2*)(C + (size_t)(m + 8) * DMODEL + n) =
                make_float2(acc[mt][nt][2], acc[mt][nt][3]);
        }
    }
}

// ================ flash attention on mma.sync (2 CTA/SM) ====================
// CTA: 128 q-rows x 1 head, 8 warps (warp = 16 q rows). K-blocks of 64.
// Q pre-scaled by TSCL. Q fragments RELOADED from smem per block (kt-outer
// loop) to cut registers under 128 -> 2 CTAs/SM co-resident.
#define FSTR 72
#define SQL  (128 * FSTR)
#define SKV  (2 * 128 * FSTR)
#define STG  (4 * 64 * FSTR)
#define OKL  (64 * FSTR)
#define OVH  (2 * 64 * FSTR)
#define OVL  (3 * 64 * FSTR)
#define FA_SMEM_BYTES ((SKV + 2 * STG) * 2)   // 110592

__global__ __launch_bounds__(256, 2) void flash_mma(
    const bf16* __restrict__ Qh, const bf16* __restrict__ Ql,
    const bf16* __restrict__ Kh, const bf16* __restrict__ Kl,
    const bf16* __restrict__ Vth, const bf16* __restrict__ Vtl,
    bf16* __restrict__ Zh, bf16* __restrict__ Zl)
{
    extern __shared__ bf16 sm[];
    const uint32_t sbase = smem_u32(sm);
    const int tid = threadIdx.x;
    const int warp = tid >> 5, lane = tid & 31;
    const int wm = warp * 16;
    const int h  = blockIdx.y;
    const int iq = gridDim.x - 1 - blockIdx.x;   // big work first

    const int c_row = tid >> 3, c_c8 = tid & 7;
    const size_t kvh = (size_t)h * SEQ * 64;
    const int nblk = 2 * iq + 2;

    // prologue: stage 0 KV
    {
        const uint32_t dst = sbase + SKV * 2;
        const size_t ks = kvh + (size_t)c_row * 64 + c_c8 * 8;
        const size_t vs = ((size_t)h * 64 + c_row) * SEQ + c_c8 * 8;
#pragma unroll
        for (int it = 0; it < 2; ++it) {
            int row = c_row + it * 32;
            uint32_t d = dst + (row * FSTR + c_c8 * 8) * 2;
            size_t k2 = ks + (size_t)it * 32 * 64;
            size_t v2 = vs + (size_t)it * 32 * SEQ;
            CP_ASYNC16(d,            Kh  + k2);
            CP_ASYNC16(d + OKL * 2,  Kl  + k2);
            CP_ASYNC16(d + OVH * 2,  Vth + v2);
            CP_ASYNC16(d + OVL * 2,  Vtl + v2);
        }
        CP_COMMIT();
    }

    // Q tiles (hi & lo) -> smem, stay there (fragments reloaded per block)
    {
        const size_t qoff = ((size_t)h * SEQ + iq * 128) * 64;
#pragma unroll
        for (int it = 0; it < 4; ++it) {
            int idx = tid + it * 256;
            int row = idx >> 3, c8 = idx & 7;
            *(uint4*)(sm + row * FSTR + c8 * 8) =
                *(const uint4*)(Qh + qoff + (size_t)row * 64 + c8 * 8);
            *(uint4*)(sm + SQL + row * FSTR + c8 * 8) =
                *(const uint4*)(Ql + qoff + (size_t)row * 64 + c8 * 8);
        }
    }
    __syncthreads();

    const uint32_t aq = sbase + ((wm + (lane & 15)) * FSTR + (lane >> 4) * 8) * 2;

    float m0 = -1.0e30f, m1 = -1.0e30f, l0 = 0.0f, l1 = 0.0f;
    float oa[8][4];
#pragma unroll
    for (int j = 0; j < 8; ++j)
#pragma unroll
        for (int t = 0; t < 4; ++t) oa[j][t] = 0.0f;

#pragma unroll 1
    for (int jk = 0; jk < nblk; ++jk) {
        const int st = jk & 1;
        if (jk + 1 < nblk) {
            const int jn = jk + 1;
            const uint32_t dst = sbase + (SKV + (jn & 1) * STG) * 2;
            const size_t ks = kvh + ((size_t)jn * 64 + c_row) * 64 + c_c8 * 8;
            const size_t vs = ((size_t)h * 64 + c_row) * SEQ + jn * 64 + c_c8 * 8;
#pragma unroll
            for (int it = 0; it < 2; ++it) {
                int row = c_row + it * 32;
                uint32_t d = dst + (row * FSTR + c_c8 * 8) * 2;
                size_t k2 = ks + (size_t)it * 32 * 64;
                size_t v2 = vs + (size_t)it * 32 * SEQ;
                CP_ASYNC16(d,            Kh  + k2);
                CP_ASYNC16(d + OKL * 2,  Kl  + k2);
                CP_ASYNC16(d + OVH * 2,  Vth + v2);
                CP_ASYNC16(d + OVL * 2,  Vtl + v2);
            }
            CP_COMMIT();
            CP_WAIT(1);
        } else {
            CP_WAIT(0);
        }
        __syncthreads();

        const uint32_t kbase = sbase + (SKV + st * STG) * 2;
        const uint32_t brow = (lane & 7) + ((lane >> 4) * 8);
        const uint32_t bcol = ((lane >> 3) & 1) * 8;

        // S = Q K^T (3-term split, q pre-scaled), kt-outer: Q frags transient
        float sa[8][4];
#pragma unroll
        for (int j = 0; j < 8; ++j)
#pragma unroll
            for (int t = 0; t < 4; ++t) sa[j][t] = 0.0f;

#pragma unroll
        for (int kt = 0; kt < 4; ++kt) {
            uint32_t qh_f[4], ql_f[4];
            ldsm_x4(qh_f, aq + kt * 32);
            ldsm_x4(ql_f, aq + SQL * 2 + kt * 32);
#pragma unroll
            for (int j = 0; j < 4; ++j) {
                const uint32_t rb = kbase + ((j * 16 + brow) * FSTR + bcol) * 2 + kt * 32;
                uint32_t bh[4], bl[4];
                ldsm_x4(bh, rb);
                ldsm_x4(bl, rb + OKL * 2);
                mma_bf16(sa[2 * j],     qh_f, bh);
                mma_bf16(sa[2 * j + 1], qh_f, bh + 2);
                mma_bf16(sa[2 * j],     ql_f, bh);
                mma_bf16(sa[2 * j + 1], ql_f, bh + 2);
                mma_bf16(sa[2 * j],     qh_f, bl);
                mma_bf16(sa[2 * j + 1], qh_f, bl + 2);
            }
        }

        // causal mask (diagonal 128x128 region only)
        if (jk >= 2 * iq) {
            const int r0 = iq * 128 + wm + (lane >> 2);
#pragma unroll
            for (int nt = 0; nt < 8; ++nt)
#pragma unroll
                for (int cc = 0; cc < 4; ++cc) {
                    int col = jk * 64 + nt * 8 + 2 * (lane & 3) + (cc & 1);
                    int row = r0 + ((cc >= 2) ? 8 : 0);
                    if (col > row) sa[nt][cc] = -1.0e30f;
                }
        }

        // online softmax
        float pm0 = -1.0e30f, pm1 = -1.0e30f;
#pragma unroll
        for (int nt = 0; nt < 8; ++nt) {
            pm0 = fmaxf(pm0, fmaxf(sa[nt][0], sa[nt][1]));
            pm1 = fmaxf(pm1, fmaxf(sa[nt][2], sa[nt][3]));
        }
        pm0 = fmaxf(pm0, __shfl_xor_sync(0xffffffffu, pm0, 1));
        pm0 = fmaxf(pm0, __shfl_xor_sync(0xffffffffu, pm0, 2));
        pm1 = fmaxf(pm1, __shfl_xor_sync(0xffffffffu, pm1, 1));
        pm1 = fmaxf(pm1, __shfl_xor_sync(0xffffffffu, pm1, 2));

        float mn0 = fmaxf(m0, pm0), mn1 = fmaxf(m1, pm1);
        float al0 = ex2f(m0 - mn0), al1 = ex2f(m1 - mn1);
        m0 = mn0; m1 = mn1;

        float rs0 = 0.0f, rs1 = 0.0f;
#pragma unroll
        for (int nt = 0; nt < 8; ++nt) {
            float p0 = ex2f(sa[nt][0] - m0);
            float p1 = ex2f(sa[nt][1] - m0);
            float p2 = ex2f(sa[nt][2] - m1);
            float p3 = ex2f(sa[nt][3] - m1);
            sa[nt][0] = p0; sa[nt][1] = p1; sa[nt][2] = p2; sa[nt][3] = p3;
            rs0 += p0 + p1; rs1 += p2 + p3;
        }
        rs0 += __shfl_xor_sync(0xffffffffu, rs0, 1);
        rs0 += __shfl_xor_sync(0xffffffffu, rs0, 2);
        rs1 += __shfl_xor_sync(0xffffffffu, rs1, 1);
        rs1 += __shfl_xor_sync(0xffffffffu, rs1, 2);
        l0 = l0 * al0 + rs0;
        l1 = l1 * al1 + rs1;
#pragma unroll
        for (int nt = 0; nt < 8; ++nt) {
            oa[nt][0] *= al0; oa[nt][1] *= al0;
            oa[nt][2] *= al1; oa[nt][3] *= al1;
        }

        // O += P V (ph*vh + pl*vh + ph*vl)
#pragma unroll
        for (int kt = 0; kt < 4; ++kt) {
            uint32_t pfh[4], pfl[4];
            {
                float a0 = sa[2 * kt][0], a1 = sa[2 * kt][1];
                float a2 = sa[2 * kt][2], a3 = sa[2 * kt][3];
                float b0 = sa[2 * kt + 1][0], b1 = sa[2 * kt + 1][1];
                float b2 = sa[2 * kt + 1][2], b3 = sa[2 * kt + 1][3];
                pfh[0] = packbf2(a0, a1);  pfh[1] = packbf2(a2, a3);
                pfh[2] = packbf2(b0, b1);  pfh[3] = packbf2(b2, b3);
                pfl[0] = packbf2(a0 - bf16rt(a0), a1 - bf16rt(a1));
                pfl[1] = packbf2(a2 - bf16rt(a2), a3 - bf16rt(a3));
                pfl[2] = packbf2(b0 - bf16rt(b0), b1 - bf16rt(b1));
                pfl[3] = packbf2(b2 - bf16rt(b2), b3 - bf16rt(b3));
            }
#pragma unroll
            for (int j = 0; j < 4; ++j) {
                const uint32_t vb = kbase + (OVH + (j * 16 + brow) * FSTR + bcol) * 2 + kt * 32;
                uint32_t vh[4], vl[4];
                ldsm_x4(vh, vb);
                ldsm_x4(vl, vb + (OVL - OVH) * 2);
                mma_bf16(oa[2 * j],     pfh, vh);
                mma_bf16(oa[2 * j + 1], pfh, vh + 2);
                mma_bf16(oa[2 * j],     pfl, vh);
                mma_bf16(oa[2 * j + 1], pfl, vh + 2);
                mma_bf16(oa[2 * j],     pfh, vl);
                mma_bf16(oa[2 * j + 1], pfh, vl + 2);
            }
        }
        __syncthreads();
    }

    // epilogue: normalize + write zh/zl splits
    const float inv0 = 1.0f / l0, inv1 = 1.0f / l1;
    const int s0 = iq * 128 + wm + (lane >> 2);
    const size_t b0 = (size_t)s0 * DMODEL + h * 64;
    const size_t b1 = b0 + 8 * DMODEL;
#pragma unroll
    for (int nt = 0; nt < 8; ++nt) {
        int e = nt * 8 + 2 * (lane & 3);
        float a0 = oa[nt][0] * inv0, a1 = oa[nt][1] * inv0;
        float a2 = oa[nt][2] * inv1, a3 = oa[nt][3] * inv1;
        *(uint32_t*)(Zh + b0 + e) = packbf2(a0, a1);
        *(uint32_t*)(Zl + b0 + e) = packbf2(a0 - bf16rt(a0), a1 - bf16rt(a1));
        *(uint32_t*)(Zh + b1 + e) = packbf2(a2, a3);
        *(uint32_t*)(Zl + b1 + e) = packbf2(a2 - bf16rt(a2), a3 - bf16rt(a3));
    }
}

// ---------------------------------------------------------------------------
extern "C" void kernel_launch(void* const* d_in, const int* in_sizes, int n_in,
                              void* d_out, int out_size)
{
    const float* x   = (const float*)d_in[0];
    const float* W_K = (const float*)d_in[1];
    const float* W_Q = (const float*)d_in[2];
    const float* W_V = (const float*)d_in[3];
    const float* W_O = (const float*)d_in[4];
    float* out = (float*)d_out;

    bf16 *qh, *ql, *kh, *kl, *vth, *vtl, *zh, *zl, *xh, *xl;
    bf16 *wqh, *wql, *wkh, *wkl, *wvh, *wvl, *woh, *wol;
    cudaGetSymbolAddress((void**)&qh, g_qh);   cudaGetSymbolAddress((void**)&ql, g_ql);
    cudaGetSymbolAddress((void**)&kh, g_kh);   cudaGetSymbolAddress((void**)&kl, g_kl);
    cudaGetSymbolAddress((void**)&vth, g_vth); cudaGetSymbolAddress((void**)&vtl, g_vtl);
    cudaGetSymbolAddress((void**)&zh, g_zh);   cudaGetSymbolAddress((void**)&zl, g_zl);
    cudaGetSymbolAddress((void**)&xh, g_xh);   cudaGetSymbolAddress((void**)&xl, g_xl);
    cudaGetSymbolAddress((void**)&wqh, g_wqh); cudaGetSymbolAddress((void**)&wql, g_wql);
    cudaGetSymbolAddress((void**)&wkh, g_wkh); cudaGetSymbolAddress((void**)&wkl, g_wkl);
    cudaGetSymbolAddress((void**)&wvh, g_wvh); cudaGetSymbolAddress((void**)&wvl, g_wvl);
    cudaGetSymbolAddress((void**)&woh, g_woh); cudaGetSymbolAddress((void**)&wol, g_wol);

    cudaFuncSetAttribute(flash_mma,
                         cudaFuncAttributeMaxDynamicSharedMemorySize, FA_SMEM_BYTES);

    const int NX4 = SEQ * DMODEL / 4;
    const int NW4 = DMODEL * DMODEL / 4;

    split_kernel<<<NX4 / 256, 256>>>(x, xh, xl, NX4, 1.0f);
    split4_kernel<<<dim3(NW4 / 256, 4), 256>>>(
        W_Q, W_K, W_V, W_O,
        wqh, wql, wkh, wkl, wvh, wvl, woh, wol, NW4);

    gemm_qkv<<<dim3(SEQ / 128, DMODEL / 128, 3), 256>>>(
        xh, xl, wqh, wql, wkh, wkl, wvh, wvl,
        qh, ql, kh, kl, vth, vtl);

    flash_mma<<<dim3(SEQ / 128, NHEAD), 256, FA_SMEM_BYTES>>>(
        qh, ql, kh, kl, vth, vtl, zh, zl);

    gemm_out<<<dim3(SEQ / 128, DMODEL / 128), 256>>>(zh, zl, woh, wol, out);
}

// round 13
// speedup vs baseline: 1.0443x; 1.0443x over previous
#include <cuda_runtime.h>
#include <cuda_bf16.h>
#include <cstdint>
#include <math.h>

#define SEQ    4096
#define DMODEL 1024
#define NHEAD  16
#define DHEAD  64

typedef __nv_bfloat16 bf16;

__device__ __forceinline__ uint32_t smem_u32(const void* p) {
    uint32_t a;
    asm("{ .reg .u64 t; cvta.to.shared.u64 t, %1; cvt.u32.u64 %0, t; }" : "=r"(a) : "l"(p));
    return a;
}
__device__ __forceinline__ void ldsm_x4(uint32_t* r, uint32_t addr) {
    asm volatile("ldmatrix.sync.aligned.m8n8.x4.shared.b16 {%0,%1,%2,%3}, [%4];"
        : "=r"(r[0]), "=r"(r[1]), "=r"(r[2]), "=r"(r[3]) : "r"(addr));
}
__device__ __forceinline__ void mma_bf16(float* c, const uint32_t* a, const uint32_t* b) {
    asm volatile(
        "mma.sync.aligned.m16n8k16.row.col.f32.bf16.bf16.f32 "
        "{%0,%1,%2,%3}, {%4,%5,%6,%7}, {%8,%9}, {%0,%1,%2,%3};"
        : "+f"(c[0]), "+f"(c[1]), "+f"(c[2]), "+f"(c[3])
        : "r"(a[0]), "r"(a[1]), "r"(a[2]), "r"(a[3]), "r"(b[0]), "r"(b[1]));
}
__device__ __forceinline__ float ex2f(float x) {
    float y; asm("ex2.approx.f32 %0,%1;" : "=f"(y) : "f"(x)); return y;
}
__device__ __forceinline__ uint32_t packbf2(float lo, float hi) {
    uint32_t d; asm("cvt.rn.bf16x2.f32 %0,%1,%2;" : "=r"(d) : "f"(hi), "f"(lo)); return d;
}
__device__ __forceinline__ float bf16rt(float x) {
    return __bfloat162float(__float2bfloat16(x));
}

#define CP_ASYNC16(dst, src) \
    asm volatile("cp.async.cg.shared.global [%0],[%1],16;" :: "r"(dst), "l"(src))
#define CP_COMMIT()  asm volatile("cp.async.commit_group;")
#define CP_WAIT(n)   asm volatile("cp.async.wait_group %0;" :: "n"(n))

#define TSCL 0.1803368801f   /* 0.125 * log2(e), folded into W_Q */

// ========================= scratch (__device__ globals) =====================
__device__ bf16 g_qh[(size_t)NHEAD * SEQ * DHEAD], g_ql[(size_t)NHEAD * SEQ * DHEAD];
__device__ bf16 g_kh[(size_t)NHEAD * SEQ * DHEAD], g_kl[(size_t)NHEAD * SEQ * DHEAD];
__device__ bf16 g_vth[(size_t)NHEAD * SEQ * DHEAD], g_vtl[(size_t)NHEAD * SEQ * DHEAD];
__device__ bf16 g_zh[(size_t)SEQ * DMODEL], g_zl[(size_t)SEQ * DMODEL];
__device__ bf16 g_xh[(size_t)SEQ * DMODEL], g_xl[(size_t)SEQ * DMODEL];
__device__ bf16 g_wqh[DMODEL * DMODEL], g_wql[DMODEL * DMODEL];
__device__ bf16 g_wkh[DMODEL * DMODEL], g_wkl[DMODEL * DMODEL];
__device__ bf16 g_wvh[DMODEL * DMODEL], g_wvl[DMODEL * DMODEL];
__device__ bf16 g_woh[DMODEL * DMODEL], g_wol[DMODEL * DMODEL];

// ============================ split kernels =================================
__global__ __launch_bounds__(256) void split_kernel(
    const float* __restrict__ in, bf16* __restrict__ hi,
    bf16* __restrict__ lo, int n4, float scale)
{
    int i = blockIdx.x * 256 + threadIdx.x;
    if (i >= n4) return;
    float4 v = ((const float4*)in)[i];
    v.x *= scale; v.y *= scale; v.z *= scale; v.w *= scale;
    uint32_t* H = (uint32_t*)hi;
    uint32_t* L = (uint32_t*)lo;
    H[2 * i]     = packbf2(v.x, v.y);
    H[2 * i + 1] = packbf2(v.z, v.w);
    L[2 * i]     = packbf2(v.x - bf16rt(v.x), v.y - bf16rt(v.y));
    L[2 * i + 1] = packbf2(v.z - bf16rt(v.z), v.w - bf16rt(v.w));
}

// 4 weight tensors in one launch; y selects {WQ(TSCL), WK, WV, WO}
__global__ __launch_bounds__(256) void split4_kernel(
    const float* __restrict__ w0, const float* __restrict__ w1,
    const float* __restrict__ w2, const float* __restrict__ w3,
    bf16* __restrict__ h0, bf16* __restrict__ l0,
    bf16* __restrict__ h1, bf16* __restrict__ l1,
    bf16* __restrict__ h2, bf16* __restrict__ l2,
    bf16* __restrict__ h3, bf16* __restrict__ l3, int n4)
{
    int i = blockIdx.x * 256 + threadIdx.x;
    if (i >= n4) return;
    const int z = blockIdx.y;
    const float* in = (z == 0) ? w0 : (z == 1) ? w1 : (z == 2) ? w2 : w3;
    bf16* hi = (z == 0) ? h0 : (z == 1) ? h1 : (z == 2) ? h2 : h3;
    bf16* lo = (z == 0) ? l0 : (z == 1) ? l1 : (z == 2) ? l2 : l3;
    const float scale = (z == 0) ? TSCL : 1.0f;
    float4 v = ((const float4*)in)[i];
    v.x *= scale; v.y *= scale; v.z *= scale; v.w *= scale;
    uint32_t* H = (uint32_t*)hi;
    uint32_t* L = (uint32_t*)lo;
    H[2 * i]     = packbf2(v.x, v.y);
    H[2 * i + 1] = packbf2(v.z, v.w);
    L[2 * i]     = packbf2(v.x - bf16rt(v.x), v.y - bf16rt(v.y));
    L[2 * i + 1] = packbf2(v.z - bf16rt(v.z), v.w - bf16rt(v.w));
}

// ====== shared GEMM mainloop (3-term split, 3-stage cp.async, 1 sync) =======
#define GSTR 40
#define ABYTES (128 * GSTR * 2)     // one A (or B) stage buffer in bytes
#define NITER 96
#define G_SMEM_BYTES (6 * ABYTES)   // 3 stages x (A + B) = 61440

__device__ __forceinline__ void gemm_issue(
    uint32_t s0, const bf16* const* Aps, const bf16* const* Bps,
    int n, int m0, int n0, int crow0, int crow1, int ccol)
{
    const int b3 = n % 3;
    const uint32_t ao = s0 + b3 * ABYTES;
    const uint32_t bo = s0 + 3 * ABYTES + b3 * ABYTES;
    const bf16* Ap = Aps[n >> 5];
    const bf16* Bp = Bps[n >> 5];
    const int k0 = (n & 31) * 32;
    CP_ASYNC16(ao + (crow0 * GSTR + ccol) * 2, Ap + (size_t)(m0 + crow0) * DMODEL + k0 + ccol);
    CP_ASYNC16(ao + (crow1 * GSTR + ccol) * 2, Ap + (size_t)(m0 + crow1) * DMODEL + k0 + ccol);
    CP_ASYNC16(bo + (crow0 * GSTR + ccol) * 2, Bp + (size_t)(n0 + crow0) * DMODEL + k0 + ccol);
    CP_ASYNC16(bo + (crow1 * GSTR + ccol) * 2, Bp + (size_t)(n0 + crow1) * DMODEL + k0 + ccol);
    CP_COMMIT();
}

__device__ __forceinline__ void gemm_core(
    const bf16* __restrict__ Ah, const bf16* __restrict__ Al,
    const bf16* __restrict__ Bh, const bf16* __restrict__ Bl,
    int m0, int n0, bf16* sm, float acc[2][8][4])
{
    const int tid  = threadIdx.x;
    const int warp = tid >> 5, lane = tid & 31;
    const int wm = (warp & 3) * 32;
    const int wn = (warp >> 2) * 64;

    const uint32_t s0 = smem_u32(sm);
    const uint32_t a_addr0 = s0 + ((wm + (lane & 15)) * GSTR + (lane >> 4) * 8) * 2;
    const uint32_t b_addr0 = s0 + 3 * ABYTES +
        ((wn + (lane & 7) + ((lane >> 4) * 8)) * GSTR + (((lane >> 3) & 1) * 8)) * 2;

    const int crow0 = tid >> 2, ccol = (tid & 3) * 8;
    const int crow1 = (tid + 256) >> 2;

    const bf16* Aps[3]; const bf16* Bps[3];
    Aps[0] = Ah; Bps[0] = Bh;  Aps[1] = Ah; Bps[1] = Bl;  Aps[2] = Al; Bps[2] = Bh;

#pragma unroll
    for (int i = 0; i < 2; ++i)
#pragma unroll
        for (int j = 0; j < 8; ++j)
#pragma unroll
            for (int t = 0; t < 4; ++t) acc[i][j][t] = 0.0f;

    // prologue: prefetch chunks 0 and 1
    gemm_issue(s0, Aps, Bps, 0, m0, n0, crow0, crow1, ccol);
    gemm_issue(s0, Aps, Bps, 1, m0, n0, crow0, crow1, ccol);

#pragma unroll 1
    for (int c = 0; c < NITER; ++c) {
        if (c + 1 < NITER) { CP_WAIT(1); } else { CP_WAIT(0); }
        __syncthreads();    // publishes chunk c; fences reads of buffer (c-1)%3
        if (c + 2 < NITER)
            gemm_issue(s0, Aps, Bps, c + 2, m0, n0, crow0, crow1, ccol);

        const uint32_t abuf = (c % 3) * ABYTES;
#pragma unroll
        for (int kk = 0; kk < 2; ++kk) {
            uint32_t a[2][4], b[8][2];
#pragma unroll
            for (int mt = 0; mt < 2; ++mt)
                ldsm_x4(a[mt], a_addr0 + abuf + (mt * 16 * GSTR + kk * 16) * 2);
#pragma unroll
            for (int j = 0; j < 4; ++j) {
                uint32_t r[4];
                ldsm_x4(r, b_addr0 + abuf + (j * 16 * GSTR + kk * 16) * 2);
                b[j * 2][0] = r[0]; b[j * 2][1] = r[1];
                b[j * 2 + 1][0] = r[2]; b[j * 2 + 1][1] = r[3];
            }
#pragma unroll
            for (int mt = 0; mt < 2; ++mt)
#pragma unroll
                for (int nt = 0; nt < 8; ++nt)
                    mma_bf16(acc[mt][nt], a[mt], b[nt]);
        }
    }
}

// ---- fused QKV projection: z selects {Q->mode1, K->mode1, V->mode2} ----
__global__ __launch_bounds__(256) void gemm_qkv(
    const bf16* __restrict__ xh, const bf16* __restrict__ xl,
    const bf16* __restrict__ wqh, const bf16* __restrict__ wql,
    const bf16* __restrict__ wkh, const bf16* __restrict__ wkl,
    const bf16* __restrict__ wvh, const bf16* __restrict__ wvl,
    bf16* __restrict__ qh, bf16* __restrict__ ql,
    bf16* __restrict__ kh, bf16* __restrict__ kl,
    bf16* __restrict__ vth, bf16* __restrict__ vtl)
{
    extern __shared__ bf16 gsm[];
    const int sel = blockIdx.z;
    const bf16* Bh = (sel == 0) ? wqh : (sel == 1) ? wkh : wvh;
    const bf16* Bl = (sel == 0) ? wql : (sel == 1) ? wkl : wvl;
    bf16* Ch = (sel == 0) ? qh : (sel == 1) ? kh : vth;
    bf16* Cl = (sel == 0) ? ql : (sel == 1) ? kl : vtl;

    const int m0 = blockIdx.x * 128;
    const int n0 = blockIdx.y * 128;
    float acc[2][8][4];
    gemm_core(xh, xl, Bh, Bl, m0, n0, gsm, acc);

    const int warp = threadIdx.x >> 5, lane = threadIdx.x & 31;
    const int wm = (warp & 3) * 32, wn = (warp >> 2) * 64;
#pragma unroll
    for (int mt = 0; mt < 2; ++mt) {
#pragma unroll
        for (int nt = 0; nt < 8; ++nt) {
            int m = m0 + wm + mt * 16 + (lane >> 2);
            int n = n0 + wn + nt * 8 + 2 * (lane & 3);
            float c0 = acc[mt][nt][0], c1 = acc[mt][nt][1];
            float c2 = acc[mt][nt][2], c3 = acc[mt][nt][3];
            if (sel != 2) {
                size_t i0 = ((size_t)(n >> 6) * SEQ + m) * 64 + (n & 63);
                *(uint32_t*)(Ch + i0) = packbf2(c0, c1);
                *(uint32_t*)(Cl + i0) = packbf2(c0 - bf16rt(c0), c1 - bf16rt(c1));
                *(uint32_t*)(Ch + i0 + 8 * 64) = packbf2(c2, c3);
                *(uint32_t*)(Cl + i0 + 8 * 64) = packbf2(c2 - bf16rt(c2), c3 - bf16rt(c3));
            } else {
                size_t b0 = ((size_t)(n >> 6) * 64 + (n & 63)) * SEQ;
                Ch[b0 + m] = __float2bfloat16(c0);
                Cl[b0 + m] = __float2bfloat16(c0 - bf16rt(c0));
                Ch[b0 + m + 8] = __float2bfloat16(c2);
                Cl[b0 + m + 8] = __float2bfloat16(c2 - bf16rt(c2));
                Ch[b0 + SEQ + m] = __float2bfloat16(c1);
                Cl[b0 + SEQ + m] = __float2bfloat16(c1 - bf16rt(c1));
                Ch[b0 + SEQ + m + 8] = __float2bfloat16(c3);
                Cl[b0 + SEQ + m + 8] = __float2bfloat16(c3 - bf16rt(c3));
            }
        }
    }
}

// ---- output projection (fp32 C) ----
__global__ __launch_bounds__(256) void gemm_out(
    const bf16* __restrict__ Ah, const bf16* __restrict__ Al,
    const bf16* __restrict__ Bh, const bf16* __restrict__ Bl,
    float* __restrict__ C)
{
    extern __shared__ bf16 gsm[];
    const int m0 = blockIdx.x * 128;
    const int n0 = blockIdx.y * 128;
    float acc[2][8][4];
    gemm_core(Ah, Al, Bh, Bl, m0, n0, gsm, acc);

    const int warp = threadIdx.x >> 5, lane = threadIdx.x & 31;
    const int wm = (warp & 3) * 32, wn = (warp >> 2) * 64;
#pragma unroll
    for (int mt = 0; mt < 2; ++mt) {
#pragma unroll
        for (int nt = 0; nt < 8; ++nt) {
            int m = m0 + wm + mt * 16 + (lane >> 2);
            int n = n0 + wn + nt * 8 + 2 * (lane & 3);
            *(float2*)(C + (size_t)m * DMODEL + n) =
                make_float2(acc[mt][nt][0], acc[mt][nt][1]);
            *(float2*)(C + (size_t)(m + 8) * DMODEL + n) =
                make_float2(acc[mt][nt][2], acc[mt][nt][3]);
        }
    }
}

// ================ flash attention on mma.sync (R11 config) ==================
// CTA: 128 q-rows x 1 head, 8 warps (warp = 16 q rows). K-blocks of 64.
// Q pre-scaled by TSCL -> scores already base-2. Q fragments register-resident.
#define FSTR 72
#define SQL  (128 * FSTR)
#define SKV  (2 * 128 * FSTR)
#define STG  (4 * 64 * FSTR)
#define OKL  (64 * FSTR)
#define OVH  (2 * 64 * FSTR)
#define OVL  (3 * 64 * FSTR)
#define FA_SMEM_BYTES ((SKV + 2 * STG) * 2)   // 110592

__global__ __launch_bounds__(256, 1) void flash_mma(
    const bf16* __restrict__ Qh, const bf16* __restrict__ Ql,
    const bf16* __restrict__ Kh, const bf16* __restrict__ Kl,
    const bf16* __restrict__ Vth, const bf16* __restrict__ Vtl,
    bf16* __restrict__ Zh, bf16* __restrict__ Zl)
{
    extern __shared__ bf16 sm[];
    const uint32_t sbase = smem_u32(sm);
    const int tid = threadIdx.x;
    const int warp = tid >> 5, lane = tid & 31;
    const int wm = warp * 16;
    const int h  = blockIdx.y;
    const int iq = gridDim.x - 1 - blockIdx.x;   // big work first

    const int c_row = tid >> 3, c_c8 = tid & 7;
    const size_t kvh = (size_t)h * SEQ * 64;
    const int nblk = 2 * iq + 2;

    // prologue: stage 0 KV
    {
        const uint32_t dst = sbase + SKV * 2;
        const size_t ks = kvh + (size_t)c_row * 64 + c_c8 * 8;
        const size_t vs = ((size_t)h * 64 + c_row) * SEQ + c_c8 * 8;
#pragma unroll
        for (int it = 0; it < 2; ++it) {
            int row = c_row + it * 32;
            uint32_t d = dst + (row * FSTR + c_c8 * 8) * 2;
            size_t k2 = ks + (size_t)it * 32 * 64;
            size_t v2 = vs + (size_t)it * 32 * SEQ;
            CP_ASYNC16(d,            Kh  + k2);
            CP_ASYNC16(d + OKL * 2,  Kl  + k2);
            CP_ASYNC16(d + OVH * 2,  Vth + v2);
            CP_ASYNC16(d + OVL * 2,  Vtl + v2);
        }
        CP_COMMIT();
    }

    // Q tiles (hi & lo)
    {
        const size_t qoff = ((size_t)h * SEQ + iq * 128) * 64;
#pragma unroll
        for (int it = 0; it < 4; ++it) {
            int idx = tid + it * 256;
            int row = idx >> 3, c8 = idx & 7;
            *(uint4*)(sm + row * FSTR + c8 * 8) =
                *(const uint4*)(Qh + qoff + (size_t)row * 64 + c8 * 8);
            *(uint4*)(sm + SQL + row * FSTR + c8 * 8) =
                *(const uint4*)(Ql + qoff + (size_t)row * 64 + c8 * 8);
        }
    }
    __syncthreads();

    uint32_t qfh[4][4], qfl[4][4];
    {
        const uint32_t aq = sbase + ((wm + (lane & 15)) * FSTR + (lane >> 4) * 8) * 2;
#pragma unroll
        for (int kt = 0; kt < 4; ++kt) {
            ldsm_x4(qfh[kt], aq + kt * 32);
            ldsm_x4(qfl[kt], aq + SQL * 2 + kt * 32);
        }
    }
    __syncthreads();

    float m0 = -1.0e30f, m1 = -1.0e30f, l0 = 0.0f, l1 = 0.0f;
    float oa[8][4];
#pragma unroll
    for (int j = 0; j < 8; ++j)
#pragma unroll
        for (int t = 0; t < 4; ++t) oa[j][t] = 0.0f;

#pragma unroll 1
    for (int jk = 0; jk < nblk; ++jk) {
        const int st = jk & 1;
        if (jk + 1 < nblk) {
            const int jn = jk + 1;
            const uint32_t dst = sbase + (SKV + (jn & 1) * STG) * 2;
            const size_t ks = kvh + ((size_t)jn * 64 + c_row) * 64 + c_c8 * 8;
            const size_t vs = ((size_t)h * 64 + c_row) * SEQ + jn * 64 + c_c8 * 8;
#pragma unroll
            for (int it = 0; it < 2; ++it) {
                int row = c_row + it * 32;
                uint32_t d = dst + (row * FSTR + c_c8 * 8) * 2;
                size_t k2 = ks + (size_t)it * 32 * 64;
                size_t v2 = vs + (size_t)it * 32 * SEQ;
                CP_ASYNC16(d,            Kh  + k2);
                CP_ASYNC16(d + OKL * 2,  Kl  + k2);
                CP_ASYNC16(d + OVH * 2,  Vth + v2);
                CP_ASYNC16(d + OVL * 2,  Vtl + v2);
            }
            CP_COMMIT();
            CP_WAIT(1);
        } else {
            CP_WAIT(0);
        }
        __syncthreads();

        const uint32_t kbase = sbase + (SKV + st * STG) * 2;
        const uint32_t brow = (lane & 7) + ((lane >> 4) * 8);
        const uint32_t bcol = ((lane >> 3) & 1) * 8;

        // S = Q K^T (3-term split, q pre-scaled)
        float sa[8][4];
#pragma unroll
        for (int j = 0; j < 8; ++j)
#pragma unroll
            for (int t = 0; t < 4; ++t) sa[j][t] = 0.0f;

#pragma unroll
        for (int j = 0; j < 4; ++j) {
            const uint32_t rb = kbase + ((j * 16 + brow) * FSTR + bcol) * 2;
#pragma unroll
            for (int kt = 0; kt < 4; ++kt) {
                uint32_t bh[4], bl[4];
                ldsm_x4(bh, rb + kt * 32);
                ldsm_x4(bl, rb + OKL * 2 + kt * 32);
                mma_bf16(sa[2 * j],     qfh[kt], bh);
                mma_bf16(sa[2 * j + 1], qfh[kt], bh + 2);
                mma_bf16(sa[2 * j],     qfl[kt], bh);
                mma_bf16(sa[2 * j + 1], qfl[kt], bh + 2);
                mma_bf16(sa[2 * j],     qfh[kt], bl);
                mma_bf16(sa[2 * j + 1], qfh[kt], bl + 2);
            }
        }

        // causal mask (diagonal 128x128 region only)
        if (jk >= 2 * iq) {
            const int r0 = iq * 128 + wm + (lane >> 2);
#pragma unroll
            for (int nt = 0; nt < 8; ++nt)
#pragma unroll
                for (int cc = 0; cc < 4; ++cc) {
                    int col = jk * 64 + nt * 8 + 2 * (lane & 3) + (cc & 1);
                    int row = r0 + ((cc >= 2) ? 8 : 0);
                    if (col > row) sa[nt][cc] = -1.0e30f;
                }
        }

        // online softmax
        float pm0 = -1.0e30f, pm1 = -1.0e30f;
#pragma unroll
        for (int nt = 0; nt < 8; ++nt) {
            pm0 = fmaxf(pm0, fmaxf(sa[nt][0], sa[nt][1]));
            pm1 = fmaxf(pm1, fmaxf(sa[nt][2], sa[nt][3]));
        }
        pm0 = fmaxf(pm0, __shfl_xor_sync(0xffffffffu, pm0, 1));
        pm0 = fmaxf(pm0, __shfl_xor_sync(0xffffffffu, pm0, 2));
        pm1 = fmaxf(pm1, __shfl_xor_sync(0xffffffffu, pm1, 1));
        pm1 = fmaxf(pm1, __shfl_xor_sync(0xffffffffu, pm1, 2));

        float mn0 = fmaxf(m0, pm0), mn1 = fmaxf(m1, pm1);
        float al0 = ex2f(m0 - mn0), al1 = ex2f(m1 - mn1);
        m0 = mn0; m1 = mn1;

        float rs0 = 0.0f, rs1 = 0.0f;
#pragma unroll
        for (int nt = 0; nt < 8; ++nt) {
            float p0 = ex2f(sa[nt][0] - m0);
            float p1 = ex2f(sa[nt][1] - m0);
            float p2 = ex2f(sa[nt][2] - m1);
            float p3 = ex2f(sa[nt][3] - m1);
            sa[nt][0] = p0; sa[nt][1] = p1; sa[nt][2] = p2; sa[nt][3] = p3;
            rs0 += p0 + p1; rs1 += p2 + p3;
        }
        rs0 += __shfl_xor_sync(0xffffffffu, rs0, 1);
        rs0 += __shfl_xor_sync(0xffffffffu, rs0, 2);
        rs1 += __shfl_xor_sync(0xffffffffu, rs1, 1);
        rs1 += __shfl_xor_sync(0xffffffffu, rs1, 2);
        l0 = l0 * al0 + rs0;
        l1 = l1 * al1 + rs1;
#pragma unroll
        for (int nt = 0; nt < 8; ++nt) {
            oa[nt][0] *= al0; oa[nt][1] *= al0;
            oa[nt][2] *= al1; oa[nt][3] *= al1;
        }

        // O += P V (ph*vh + pl*vh + ph*vl)
#pragma unroll
        for (int kt = 0; kt < 4; ++kt) {
            uint32_t pfh[4], pfl[4];
            {
                float a0 = sa[2 * kt][0], a1 = sa[2 * kt][1];
                float a2 = sa[2 * kt][2], a3 = sa[2 * kt][3];
                float b0 = sa[2 * kt + 1][0], b1 = sa[2 * kt + 1][1];
                float b2 = sa[2 * kt + 1][2], b3 = sa[2 * kt + 1][3];
                pfh[0] = packbf2(a0, a1);  pfh[1] = packbf2(a2, a3);
                pfh[2] = packbf2(b0, b1);  pfh[3] = packbf2(b2, b3);
                pfl[0] = packbf2(a0 - bf16rt(a0), a1 - bf16rt(a1));
                pfl[1] = packbf2(a2 - bf16rt(a2), a3 - bf16rt(a3));
                pfl[2] = packbf2(b0 - bf16rt(b0), b1 - bf16rt(b1));
                pfl[3] = packbf2(b2 - bf16rt(b2), b3 - bf16rt(b3));
            }
#pragma unroll
            for (int j = 0; j < 4; ++j) {
                const uint32_t vb = kbase + (OVH + (j * 16 + brow) * FSTR + bcol) * 2 + kt * 32;
                uint32_t vh[4], vl[4];
                ldsm_x4(vh, vb);
                ldsm_x4(vl, vb + (OVL - OVH) * 2);
                mma_bf16(oa[2 * j],     pfh, vh);
                mma_bf16(oa[2 * j + 1], pfh, vh + 2);
                mma_bf16(oa[2 * j],     pfl, vh);
                mma_bf16(oa[2 * j + 1], pfl, vh + 2);
                mma_bf16(oa[2 * j],     pfh, vl);
                mma_bf16(oa[2 * j + 1], pfh, vl + 2);
            }
        }
        __syncthreads();
    }

    // epilogue: normalize + write zh/zl splits
    const float inv0 = 1.0f / l0, inv1 = 1.0f / l1;
    const int s0 = iq * 128 + wm + (lane >> 2);
    const size_t b0 = (size_t)s0 * DMODEL + h * 64;
    const size_t b1 = b0 + 8 * DMODEL;
#pragma unroll
    for (int nt = 0; nt < 8; ++nt) {
        int e = nt * 8 + 2 * (lane & 3);
        float a0 = oa[nt][0] * inv0, a1 = oa[nt][1] * inv0;
        float a2 = oa[nt][2] * inv1, a3 = oa[nt][3] * inv1;
        *(uint32_t*)(Zh + b0 + e) = packbf2(a0, a1);
        *(uint32_t*)(Zl + b0 + e) = packbf2(a0 - bf16rt(a0), a1 - bf16rt(a1));
        *(uint32_t*)(Zh + b1 + e) = packbf2(a2, a3);
        *(uint32_t*)(Zl + b1 + e) = packbf2(a2 - bf16rt(a2), a3 - bf16rt(a3));
    }
}

// ---------------------------------------------------------------------------
extern "C" void kernel_launch(void* const* d_in, const int* in_sizes, int n_in,
                              void* d_out, int out_size)
{
    const float* x   = (const float*)d_in[0];
    const float* W_K = (const float*)d_in[1];
    const float* W_Q = (const float*)d_in[2];
    const float* W_V = (const float*)d_in[3];
    const float* W_O = (const float*)d_in[4];
    float* out = (float*)d_out;

    bf16 *qh, *ql, *kh, *kl, *vth, *vtl, *zh, *zl, *xh, *xl;
    bf16 *wqh, *wql, *wkh, *wkl, *wvh, *wvl, *woh, *wol;
    cudaGetSymbolAddress((void**)&qh, g_qh);   cudaGetSymbolAddress((void**)&ql, g_ql);
    cudaGetSymbolAddress((void**)&kh, g_kh);   cudaGetSymbolAddress((void**)&kl, g_kl);
    cudaGetSymbolAddress((void**)&vth, g_vth); cudaGetSymbolAddress((void**)&vtl, g_vtl);
    cudaGetSymbolAddress((void**)&zh, g_zh);   cudaGetSymbolAddress((void**)&zl, g_zl);
    cudaGetSymbolAddress((void**)&xh, g_xh);   cudaGetSymbolAddress((void**)&xl, g_xl);
    cudaGetSymbolAddress((void**)&wqh, g_wqh); cudaGetSymbolAddress((void**)&wql, g_wql);
    cudaGetSymbolAddress((void**)&wkh, g_wkh); cudaGetSymbolAddress((void**)&wkl, g_wkl);
    cudaGetSymbolAddress((void**)&wvh, g_wvh); cudaGetSymbolAddress((void**)&wvl, g_wvl);
    cudaGetSymbolAddress((void**)&woh, g_woh); cudaGetSymbolAddress((void**)&wol, g_wol);

    cudaFuncSetAttribute(flash_mma,
                         cudaFuncAttributeMaxDynamicSharedMemorySize, FA_SMEM_BYTES);
    cudaFuncSetAttribute(gemm_qkv,
                         cudaFuncAttributeMaxDynamicSharedMemorySize, G_SMEM_BYTES);
    cudaFuncSetAttribute(gemm_out,
                         cudaFuncAttributeMaxDynamicSharedMemorySize, G_SMEM_BYTES);

    const int NX4 = SEQ * DMODEL / 4;
    const int NW4 = DMODEL * DMODEL / 4;

    split_kernel<<<NX4 / 256, 256>>>(x, xh, xl, NX4, 1.0f);
    split4_kernel<<<dim3(NW4 / 256, 4), 256>>>(
        W_Q, W_K, W_V, W_O,
        wqh, wql, wkh, wkl, wvh, wvl, woh, wol, NW4);

    gemm_qkv<<<dim3(SEQ / 128, DMODEL / 128, 3), 256, G_SMEM_BYTES>>>(
        xh, xl, wqh, wql, wkh, wkl, wvh, wvl,
        qh, ql, kh, kl, vth, vtl);

    flash_mma<<<dim3(SEQ / 128, NHEAD), 256, FA_SMEM_BYTES>>>(
        qh, ql, kh, kl, vth, vtl, zh, zl);

    gemm_out<<<dim3(SEQ / 128, DMODEL / 128), 256, G_SMEM_BYTES>>>(zh, zl, woh, wol, out);
}

// round 14
// speedup vs baseline: 1.2081x; 1.1568x over previous
#include <cuda_runtime.h>
#include <cuda_bf16.h>
#include <cuda_fp16.h>
#include <cstdint>
#include <math.h>

#define SEQ    4096
#define DMODEL 1024
#define NHEAD  16
#define DHEAD  64

typedef __nv_bfloat16 bf16;

__device__ __forceinline__ uint32_t smem_u32(const void* p) {
    uint32_t a;
    asm("{ .reg .u64 t; cvta.to.shared.u64 t, %1; cvt.u32.u64 %0, t; }" : "=r"(a) : "l"(p));
    return a;
}
__device__ __forceinline__ void ldsm_x4(uint32_t* r, uint32_t addr) {
    asm volatile("ldmatrix.sync.aligned.m8n8.x4.shared.b16 {%0,%1,%2,%3}, [%4];"
        : "=r"(r[0]), "=r"(r[1]), "=r"(r[2]), "=r"(r[3]) : "r"(addr));
}
__device__ __forceinline__ void mma_bf16(float* c, const uint32_t* a, const uint32_t* b) {
    asm volatile(
        "mma.sync.aligned.m16n8k16.row.col.f32.bf16.bf16.f32 "
        "{%0,%1,%2,%3}, {%4,%5,%6,%7}, {%8,%9}, {%0,%1,%2,%3};"
        : "+f"(c[0]), "+f"(c[1]), "+f"(c[2]), "+f"(c[3])
        : "r"(a[0]), "r"(a[1]), "r"(a[2]), "r"(a[3]), "r"(b[0]), "r"(b[1]));
}
__device__ __forceinline__ void mma_f16(float* c, const uint32_t* a, const uint32_t* b) {
    asm volatile(
        "mma.sync.aligned.m16n8k16.row.col.f32.f16.f16.f32 "
        "{%0,%1,%2,%3}, {%4,%5,%6,%7}, {%8,%9}, {%0,%1,%2,%3};"
        : "+f"(c[0]), "+f"(c[1]), "+f"(c[2]), "+f"(c[3])
        : "r"(a[0]), "r"(a[1]), "r"(a[2]), "r"(a[3]), "r"(b[0]), "r"(b[1]));
}
__device__ __forceinline__ float ex2f(float x) {
    float y; asm("ex2.approx.f32 %0,%1;" : "=f"(y) : "f"(x)); return y;
}
__device__ __forceinline__ uint32_t packbf2(float lo, float hi) {
    uint32_t d; asm("cvt.rn.bf16x2.f32 %0,%1,%2;" : "=r"(d) : "f"(hi), "f"(lo)); return d;
}
__device__ __forceinline__ uint32_t packh2(float lo, float hi) {
    uint32_t d; asm("cvt.rn.f16x2.f32 %0,%1,%2;" : "=r"(d) : "f"(hi), "f"(lo)); return d;
}
__device__ __forceinline__ float bf16rt(float x) {
    return __bfloat162float(__float2bfloat16(x));
}
__device__ __forceinline__ float f16rt(float x) {
    return __half2float(__float2half_rn(x));
}

#define CP_ASYNC16(dst, src) \
    asm volatile("cp.async.cg.shared.global [%0],[%1],16;" :: "r"(dst), "l"(src))
#define CP_COMMIT()  asm volatile("cp.async.commit_group;")
#define CP_WAIT(n)   asm volatile("cp.async.wait_group %0;" :: "n"(n))

#define TSCL 0.1803368801f   /* 0.125 * log2(e), folded into W_Q */

// ========================= scratch (__device__ globals) =====================
// q: fp16 split pair; k: single fp16; v: single fp16 transposed (bit-stored
// in bf16-typed arrays; all accesses are typeless 16-bit).
__device__ bf16 g_qh[(size_t)NHEAD * SEQ * DHEAD], g_ql[(size_t)NHEAD * SEQ * DHEAD];
__device__ bf16 g_kh[(size_t)NHEAD * SEQ * DHEAD];
__device__ bf16 g_vth[(size_t)NHEAD * SEQ * DHEAD];
__device__ bf16 g_zh[(size_t)SEQ * DMODEL], g_zl[(size_t)SEQ * DMODEL];
__device__ bf16 g_xh[(size_t)SEQ * DMODEL], g_xl[(size_t)SEQ * DMODEL];
__device__ bf16 g_wqh[DMODEL * DMODEL], g_wql[DMODEL * DMODEL];
__device__ bf16 g_wkh[DMODEL * DMODEL], g_wkl[DMODEL * DMODEL];
__device__ bf16 g_wvh[DMODEL * DMODEL], g_wvl[DMODEL * DMODEL];
__device__ bf16 g_woh[DMODEL * DMODEL], g_wol[DMODEL * DMODEL];

// ============================ split kernels =================================
__global__ __launch_bounds__(256) void split_kernel(
    const float* __restrict__ in, bf16* __restrict__ hi,
    bf16* __restrict__ lo, int n4, float scale)
{
    int i = blockIdx.x * 256 + threadIdx.x;
    if (i >= n4) return;
    float4 v = ((const float4*)in)[i];
    v.x *= scale; v.y *= scale; v.z *= scale; v.w *= scale;
    uint32_t* H = (uint32_t*)hi;
    uint32_t* L = (uint32_t*)lo;
    H[2 * i]     = packbf2(v.x, v.y);
    H[2 * i + 1] = packbf2(v.z, v.w);
    L[2 * i]     = packbf2(v.x - bf16rt(v.x), v.y - bf16rt(v.y));
    L[2 * i + 1] = packbf2(v.z - bf16rt(v.z), v.w - bf16rt(v.w));
}

// 4 weight tensors in one launch; y selects {WQ(TSCL), WK, WV, WO}
__global__ __launch_bounds__(256) void split4_kernel(
    const float* __restrict__ w0, const float* __restrict__ w1,
    const float* __restrict__ w2, const float* __restrict__ w3,
    bf16* __restrict__ h0, bf16* __restrict__ l0,
    bf16* __restrict__ h1, bf16* __restrict__ l1,
    bf16* __restrict__ h2, bf16* __restrict__ l2,
    bf16* __restrict__ h3, bf16* __restrict__ l3, int n4)
{
    int i = blockIdx.x * 256 + threadIdx.x;
    if (i >= n4) return;
    const int z = blockIdx.y;
    const float* in = (z == 0) ? w0 : (z == 1) ? w1 : (z == 2) ? w2 : w3;
    bf16* hi = (z == 0) ? h0 : (z == 1) ? h1 : (z == 2) ? h2 : h3;
    bf16* lo = (z == 0) ? l0 : (z == 1) ? l1 : (z == 2) ? l2 : l3;
    const float scale = (z == 0) ? TSCL : 1.0f;
    float4 v = ((const float4*)in)[i];
    v.x *= scale; v.y *= scale; v.z *= scale; v.w *= scale;
    uint32_t* H = (uint32_t*)hi;
    uint32_t* L = (uint32_t*)lo;
    H[2 * i]     = packbf2(v.x, v.y);
    H[2 * i + 1] = packbf2(v.z, v.w);
    L[2 * i]     = packbf2(v.x - bf16rt(v.x), v.y - bf16rt(v.y));
    L[2 * i + 1] = packbf2(v.z - bf16rt(v.z), v.w - bf16rt(v.w));
}

// ====== shared GEMM mainloop (3-term split, 3-stage cp.async, 1 sync) =======
#define GSTR 40
#define ABYTES (128 * GSTR * 2)     // one A (or B) stage buffer in bytes
#define NITER 96
#define G_SMEM_BYTES (6 * ABYTES)   // 3 stages x (A + B) = 61440

__device__ __forceinline__ void gemm_issue(
    uint32_t s0, const bf16* const* Aps, const bf16* const* Bps,
    int n, int m0, int n0, int crow0, int crow1, int ccol)
{
    const int b3 = n % 3;
    const uint32_t ao = s0 + b3 * ABYTES;
    const uint32_t bo = s0 + 3 * ABYTES + b3 * ABYTES;
    const bf16* Ap = Aps[n >> 5];
    const bf16* Bp = Bps[n >> 5];
    const int k0 = (n & 31) * 32;
    CP_ASYNC16(ao + (crow0 * GSTR + ccol) * 2, Ap + (size_t)(m0 + crow0) * DMODEL + k0 + ccol);
    CP_ASYNC16(ao + (crow1 * GSTR + ccol) * 2, Ap + (size_t)(m0 + crow1) * DMODEL + k0 + ccol);
    CP_ASYNC16(bo + (crow0 * GSTR + ccol) * 2, Bp + (size_t)(n0 + crow0) * DMODEL + k0 + ccol);
    CP_ASYNC16(bo + (crow1 * GSTR + ccol) * 2, Bp + (size_t)(n0 + crow1) * DMODEL + k0 + ccol);
    CP_COMMIT();
}

__device__ __forceinline__ void gemm_core(
    const bf16* __restrict__ Ah, const bf16* __restrict__ Al,
    const bf16* __restrict__ Bh, const bf16* __restrict__ Bl,
    int m0, int n0, bf16* sm, float acc[2][8][4])
{
    const int tid  = threadIdx.x;
    const int warp = tid >> 5, lane = tid & 31;
    const int wm = (warp & 3) * 32;
    const int wn = (warp >> 2) * 64;

    const uint32_t s0 = smem_u32(sm);
    const uint32_t a_addr0 = s0 + ((wm + (lane & 15)) * GSTR + (lane >> 4) * 8) * 2;
    const uint32_t b_addr0 = s0 + 3 * ABYTES +
        ((wn + (lane & 7) + ((lane >> 4) * 8)) * GSTR + (((lane >> 3) & 1) * 8)) * 2;

    const int crow0 = tid >> 2, ccol = (tid & 3) * 8;
    const int crow1 = (tid + 256) >> 2;

    const bf16* Aps[3]; const bf16* Bps[3];
    Aps[0] = Ah; Bps[0] = Bh;  Aps[1] = Ah; Bps[1] = Bl;  Aps[2] = Al; Bps[2] = Bh;

#pragma unroll
    for (int i = 0; i < 2; ++i)
#pragma unroll
        for (int j = 0; j < 8; ++j)
#pragma unroll
            for (int t = 0; t < 4; ++t) acc[i][j][t] = 0.0f;

    gemm_issue(s0, Aps, Bps, 0, m0, n0, crow0, crow1, ccol);
    gemm_issue(s0, Aps, Bps, 1, m0, n0, crow0, crow1, ccol);

#pragma unroll 1
    for (int c = 0; c < NITER; ++c) {
        if (c + 1 < NITER) { CP_WAIT(1); } else { CP_WAIT(0); }
        __syncthreads();
        if (c + 2 < NITER)
            gemm_issue(s0, Aps, Bps, c + 2, m0, n0, crow0, crow1, ccol);

        const uint32_t abuf = (c % 3) * ABYTES;
#pragma unroll
        for (int kk = 0; kk < 2; ++kk) {
            uint32_t a[2][4], b[8][2];
#pragma unroll
            for (int mt = 0; mt < 2; ++mt)
                ldsm_x4(a[mt], a_addr0 + abuf + (mt * 16 * GSTR + kk * 16) * 2);
#pragma unroll
            for (int j = 0; j < 4; ++j) {
                uint32_t r[4];
                ldsm_x4(r, b_addr0 + abuf + (j * 16 * GSTR + kk * 16) * 2);
                b[j * 2][0] = r[0]; b[j * 2][1] = r[1];
                b[j * 2 + 1][0] = r[2]; b[j * 2 + 1][1] = r[3];
            }
#pragma unroll
            for (int mt = 0; mt < 2; ++mt)
#pragma unroll
                for (int nt = 0; nt < 8; ++nt)
                    mma_bf16(acc[mt][nt], a[mt], b[nt]);
        }
    }
}

// ---- fused QKV projection: z selects {Q->fp16 split, K->fp16, V->fp16 T} ----
__global__ __launch_bounds__(256) void gemm_qkv(
    const bf16* __restrict__ xh, const bf16* __restrict__ xl,
    const bf16* __restrict__ wqh, const bf16* __restrict__ wql,
    const bf16* __restrict__ wkh, const bf16* __restrict__ wkl,
    const bf16* __restrict__ wvh, const bf16* __restrict__ wvl,
    bf16* __restrict__ qh, bf16* __restrict__ ql,
    bf16* __restrict__ kh, bf16* __restrict__ vth)
{
    extern __shared__ bf16 gsm[];
    const int sel = blockIdx.z;
    const bf16* Bh = (sel == 0) ? wqh : (sel == 1) ? wkh : wvh;
    const bf16* Bl = (sel == 0) ? wql : (sel == 1) ? wkl : wvl;

    const int m0 = blockIdx.x * 128;
    const int n0 = blockIdx.y * 128;
    float acc[2][8][4];
    gemm_core(xh, xl, Bh, Bl, m0, n0, gsm, acc);

    const int warp = threadIdx.x >> 5, lane = threadIdx.x & 31;
    const int wm = (warp & 3) * 32, wn = (warp >> 2) * 64;
#pragma unroll
    for (int mt = 0; mt < 2; ++mt) {
#pragma unroll
        for (int nt = 0; nt < 8; ++nt) {
            int m = m0 + wm + mt * 16 + (lane >> 2);
            int n = n0 + wn + nt * 8 + 2 * (lane & 3);
            float c0 = acc[mt][nt][0], c1 = acc[mt][nt][1];
            float c2 = acc[mt][nt][2], c3 = acc[mt][nt][3];
            if (sel == 0) {          // Q: fp16 split pair
                size_t i0 = ((size_t)(n >> 6) * SEQ + m) * 64 + (n & 63);
                *(uint32_t*)(qh + i0) = packh2(c0, c1);
                *(uint32_t*)(ql + i0) = packh2(c0 - f16rt(c0), c1 - f16rt(c1));
                *(uint32_t*)(qh + i0 + 8 * 64) = packh2(c2, c3);
                *(uint32_t*)(ql + i0 + 8 * 64) = packh2(c2 - f16rt(c2), c3 - f16rt(c3));
            } else if (sel == 1) {   // K: single fp16
                size_t i0 = ((size_t)(n >> 6) * SEQ + m) * 64 + (n & 63);
                *(uint32_t*)(kh + i0) = packh2(c0, c1);
                *(uint32_t*)(kh + i0 + 8 * 64) = packh2(c2, c3);
            } else {                 // V: single fp16, transposed [H][64][S]
                size_t b0 = ((size_t)(n >> 6) * 64 + (n & 63)) * SEQ;
                *(__half*)(vth + b0 + m)           = __float2half_rn(c0);
                *(__half*)(vth + b0 + m + 8)       = __float2half_rn(c2);
                *(__half*)(vth + b0 + SEQ + m)     = __float2half_rn(c1);
                *(__half*)(vth + b0 + SEQ + m + 8) = __float2half_rn(c3);
            }
        }
    }
}

// ---- output projection (fp32 C, bf16 3-term) ----
__global__ __launch_bounds__(256) void gemm_out(
    const bf16* __restrict__ Ah, const bf16* __restrict__ Al,
    const bf16* __restrict__ Bh, const bf16* __restrict__ Bl,
    float* __restrict__ C)
{
    extern __shared__ bf16 gsm[];
    const int m0 = blockIdx.x * 128;
    const int n0 = blockIdx.y * 128;
    float acc[2][8][4];
    gemm_core(Ah, Al, Bh, Bl, m0, n0, gsm, acc);

    const int warp = threadIdx.x >> 5, lane = threadIdx.x & 31;
    const int wm = (warp & 3) * 32, wn = (warp >> 2) * 64;
#pragma unroll
    for (int mt = 0; mt < 2; ++mt) {
#pragma unroll
        for (int nt = 0; nt < 8; ++nt) {
            int m = m0 + wm + mt * 16 + (lane >> 2);
            int n = n0 + wn + nt * 8 + 2 * (lane & 3);
            *(float2*)(C + (size_t)m * DMODEL + n) =
                make_float2(acc[mt][nt][0], acc[mt][nt][1]);
            *(float2*)(C + (size_t)(m + 8) * DMODEL + n) =
                make_float2(acc[mt][nt][2], acc[mt][nt][3]);
        }
    }
}

// ======== flash attention: fp16 asymmetric (q/p split, k/v single) ==========
// CTA: 128 q-rows x 1 head, 8 warps. K-blocks of 64. Q pre-scaled by TSCL.
// Smem: qh 128x72 | ql 128x72 | 2 stages x {k 64x72, vt 64x72}  (fp16 bits)
#define FSTR 72
#define SQL  (128 * FSTR)
#define SKV  (2 * 128 * FSTR)
#define STG  (2 * 64 * FSTR)
#define OV   (64 * FSTR)
#define FA_SMEM_BYTES ((SKV + 2 * STG) * 2)   // 73728

__global__ __launch_bounds__(256, 1) void flash_mma(
    const bf16* __restrict__ Qh, const bf16* __restrict__ Ql,
    const bf16* __restrict__ Kh, const bf16* __restrict__ Vth,
    bf16* __restrict__ Zh, bf16* __restrict__ Zl)
{
    extern __shared__ bf16 sm[];
    const uint32_t sbase = smem_u32(sm);
    const int tid = threadIdx.x;
    const int warp = tid >> 5, lane = tid & 31;
    const int wm = warp * 16;
    const int h  = blockIdx.y;
    const int iq = gridDim.x - 1 - blockIdx.x;   // big work first

    const int c_row = tid >> 3, c_c8 = tid & 7;
    const size_t kvh = (size_t)h * SEQ * 64;
    const int nblk = 2 * iq + 2;

    // prologue: stage 0 KV
    {
        const uint32_t dst = sbase + SKV * 2;
        const size_t ks = kvh + (size_t)c_row * 64 + c_c8 * 8;
        const size_t vs = ((size_t)h * 64 + c_row) * SEQ + c_c8 * 8;
#pragma unroll
        for (int it = 0; it < 2; ++it) {
            int row = c_row + it * 32;
            uint32_t d = dst + (row * FSTR + c_c8 * 8) * 2;
            CP_ASYNC16(d,           Kh  + ks + (size_t)it * 32 * 64);
            CP_ASYNC16(d + OV * 2,  Vth + vs + (size_t)it * 32 * SEQ);
        }
        CP_COMMIT();
    }

    // Q tiles (fp16 hi & lo)
    {
        const size_t qoff = ((size_t)h * SEQ + iq * 128) * 64;
#pragma unroll
        for (int it = 0; it < 4; ++it) {
            int idx = tid + it * 256;
            int row = idx >> 3, c8 = idx & 7;
            *(uint4*)(sm + row * FSTR + c8 * 8) =
                *(const uint4*)(Qh + qoff + (size_t)row * 64 + c8 * 8);
            *(uint4*)(sm + SQL + row * FSTR + c8 * 8) =
                *(const uint4*)(Ql + qoff + (size_t)row * 64 + c8 * 8);
        }
    }
    __syncthreads();

    uint32_t qfh[4][4], qfl[4][4];
    {
        const uint32_t aq = sbase + ((wm + (lane & 15)) * FSTR + (lane >> 4) * 8) * 2;
#pragma unroll
        for (int kt = 0; kt < 4; ++kt) {
            ldsm_x4(qfh[kt], aq + kt * 32);
            ldsm_x4(qfl[kt], aq + SQL * 2 + kt * 32);
        }
    }
    __syncthreads();

    float m0 = -1.0e30f, m1 = -1.0e30f, l0 = 0.0f, l1 = 0.0f;
    float oa[8][4];
#pragma unroll
    for (int j = 0; j < 8; ++j)
#pragma unroll
        for (int t = 0; t < 4; ++t) oa[j][t] = 0.0f;

#pragma unroll 1
    for (int jk = 0; jk < nblk; ++jk) {
        const int st = jk & 1;
        if (jk + 1 < nblk) {
            const int jn = jk + 1;
            const uint32_t dst = sbase + (SKV + (jn & 1) * STG) * 2;
            const size_t ks = kvh + ((size_t)jn * 64 + c_row) * 64 + c_c8 * 8;
            const size_t vs = ((size_t)h * 64 + c_row) * SEQ + jn * 64 + c_c8 * 8;
#pragma unroll
            for (int it = 0; it < 2; ++it) {
                int row = c_row + it * 32;
                uint32_t d = dst + (row * FSTR + c_c8 * 8) * 2;
                CP_ASYNC16(d,           Kh  + ks + (size_t)it * 32 * 64);
                CP_ASYNC16(d + OV * 2,  Vth + vs + (size_t)it * 32 * SEQ);
            }
            CP_COMMIT();
            CP_WAIT(1);
        } else {
            CP_WAIT(0);
        }
        __syncthreads();

        const uint32_t kbase = sbase + (SKV + st * STG) * 2;
        const uint32_t brow = (lane & 7) + ((lane >> 4) * 8);
        const uint32_t bcol = ((lane >> 3) & 1) * 8;

        // S = Q K^T : qh*k + ql*k  (fp16, q pre-scaled)
        float sa[8][4];
#pragma unroll
        for (int j = 0; j < 8; ++j)
#pragma unroll
            for (int t = 0; t < 4; ++t) sa[j][t] = 0.0f;

#pragma unroll
        for (int j = 0; j < 4; ++j) {
            const uint32_t rb = kbase + ((j * 16 + brow) * FSTR + bcol) * 2;
#pragma unroll
            for (int kt = 0; kt < 4; ++kt) {
                uint32_t bh[4];
                ldsm_x4(bh, rb + kt * 32);
                mma_f16(sa[2 * j],     qfh[kt], bh);
                mma_f16(sa[2 * j + 1], qfh[kt], bh + 2);
                mma_f16(sa[2 * j],     qfl[kt], bh);
                mma_f16(sa[2 * j + 1], qfl[kt], bh + 2);
            }
        }

        // causal mask (diagonal 128x128 region only)
        if (jk >= 2 * iq) {
            const int r0 = iq * 128 + wm + (lane >> 2);
#pragma unroll
            for (int nt = 0; nt < 8; ++nt)
#pragma unroll
                for (int cc = 0; cc < 4; ++cc) {
                    int col = jk * 64 + nt * 8 + 2 * (lane & 3) + (cc & 1);
                    int row = r0 + ((cc >= 2) ? 8 : 0);
                    if (col > row) sa[nt][cc] = -1.0e30f;
                }
        }

        // online softmax
        float pm0 = -1.0e30f, pm1 = -1.0e30f;
#pragma unroll
        for (int nt = 0; nt < 8; ++nt) {
            pm0 = fmaxf(pm0, fmaxf(sa[nt][0], sa[nt][1]));
            pm1 = fmaxf(pm1, fmaxf(sa[nt][2], sa[nt][3]));
        }
        pm0 = fmaxf(pm0, __shfl_xor_sync(0xffffffffu, pm0, 1));
        pm0 = fmaxf(pm0, __shfl_xor_sync(0xffffffffu, pm0, 2));
        pm1 = fmaxf(pm1, __shfl_xor_sync(0xffffffffu, pm1, 1));
        pm1 = fmaxf(pm1, __shfl_xor_sync(0xffffffffu, pm1, 2));

        float mn0 = fmaxf(m0, pm0), mn1 = fmaxf(m1, pm1);
        float al0 = ex2f(m0 - mn0), al1 = ex2f(m1 - mn1);
        m0 = mn0; m1 = mn1;

        float rs0 = 0.0f, rs1 = 0.0f;
#pragma unroll
        for (int nt = 0; nt < 8; ++nt) {
            float p0 = ex2f(sa[nt][0] - m0);
            float p1 = ex2f(sa[nt][1] - m0);
            float p2 = ex2f(sa[nt][2] - m1);
            float p3 = ex2f(sa[nt][3] - m1);
            sa[nt][0] = p0; sa[nt][1] = p1; sa[nt][2] = p2; sa[nt][3] = p3;
            rs0 += p0 + p1; rs1 += p2 + p3;
        }
        rs0 += __shfl_xor_sync(0xffffffffu, rs0, 1);
        rs0 += __shfl_xor_sync(0xffffffffu, rs0, 2);
        rs1 += __shfl_xor_sync(0xffffffffu, rs1, 1);
        rs1 += __shfl_xor_sync(0xffffffffu, rs1, 2);
        l0 = l0 * al0 + rs0;
        l1 = l1 * al1 + rs1;
#pragma unroll
        for (int nt = 0; nt < 8; ++nt) {
            oa[nt][0] *= al0; oa[nt][1] *= al0;
            oa[nt][2] *= al1; oa[nt][3] *= al1;
        }

        // O += P V : ph*v + pl*v  (fp16 P split, single fp16 V)
#pragma unroll
        for (int kt = 0; kt < 4; ++kt) {
            uint32_t pfh[4], pfl[4];
            {
                float a0 = sa[2 * kt][0], a1 = sa[2 * kt][1];
                float a2 = sa[2 * kt][2], a3 = sa[2 * kt][3];
                float b0 = sa[2 * kt + 1][0], b1 = sa[2 * kt + 1][1];
                float b2 = sa[2 * kt + 1][2], b3 = sa[2 * kt + 1][3];
                pfh[0] = packh2(a0, a1);  pfh[1] = packh2(a2, a3);
                pfh[2] = packh2(b0, b1);  pfh[3] = packh2(b2, b3);
                pfl[0] = packh2(a0 - f16rt(a0), a1 - f16rt(a1));
                pfl[1] = packh2(a2 - f16rt(a2), a3 - f16rt(a3));
                pfl[2] = packh2(b0 - f16rt(b0), b1 - f16rt(b1));
                pfl[3] = packh2(b2 - f16rt(b2), b3 - f16rt(b3));
            }
#pragma unroll
            for (int j = 0; j < 4; ++j) {
                const uint32_t vb = kbase + (OV + (j * 16 + brow) * FSTR + bcol) * 2 + kt * 32;
                uint32_t vh[4];
                ldsm_x4(vh, vb);
                mma_f16(oa[2 * j],     pfh, vh);
                mma_f16(oa[2 * j + 1], pfh, vh + 2);
                mma_f16(oa[2 * j],     pfl, vh);
                mma_f16(oa[2 * j + 1], pfl, vh + 2);
            }
        }
        __syncthreads();
    }

    // epilogue: normalize + write zh/zl bf16 splits (out gemm stays bf16)
    const float inv0 = 1.0f / l0, inv1 = 1.0f / l1;
    const int s0 = iq * 128 + wm + (lane >> 2);
    const size_t b0 = (size_t)s0 * DMODEL + h * 64;
    const size_t b1 = b0 + 8 * DMODEL;
#pragma unroll
    for (int nt = 0; nt < 8; ++nt) {
        int e = nt * 8 + 2 * (lane & 3);
        float a0 = oa[nt][0] * inv0, a1 = oa[nt][1] * inv0;
        float a2 = oa[nt][2] * inv1, a3 = oa[nt][3] * inv1;
        *(uint32_t*)(Zh + b0 + e) = packbf2(a0, a1);
        *(uint32_t*)(Zl + b0 + e) = packbf2(a0 - bf16rt(a0), a1 - bf16rt(a1));
        *(uint32_t*)(Zh + b1 + e) = packbf2(a2, a3);
        *(uint32_t*)(Zl + b1 + e) = packbf2(a2 - bf16rt(a2), a3 - bf16rt(a3));
    }
}

// ---------------------------------------------------------------------------
extern "C" void kernel_launch(void* const* d_in, const int* in_sizes, int n_in,
                              void* d_out, int out_size)
{
    const float* x   = (const float*)d_in[0];
    const float* W_K = (const float*)d_in[1];
    const float* W_Q = (const float*)d_in[2];
    const float* W_V = (const float*)d_in[3];
    const float* W_O = (const float*)d_in[4];
    float* out = (float*)d_out;

    bf16 *qh, *ql, *kh, *vth, *zh, *zl, *xh, *xl;
    bf16 *wqh, *wql, *wkh, *wkl, *wvh, *wvl, *woh, *wol;
    cudaGetSymbolAddress((void**)&qh, g_qh);   cudaGetSymbolAddress((void**)&ql, g_ql);
    cudaGetSymbolAddress((void**)&kh, g_kh);
    cudaGetSymbolAddress((void**)&vth, g_vth);
    cudaGetSymbolAddress((void**)&zh, g_zh);   cudaGetSymbolAddress((void**)&zl, g_zl);
    cudaGetSymbolAddress((void**)&xh, g_xh);   cudaGetSymbolAddress((void**)&xl, g_xl);
    cudaGetSymbolAddress((void**)&wqh, g_wqh); cudaGetSymbolAddress((void**)&wql, g_wql);
    cudaGetSymbolAddress((void**)&wkh, g_wkh); cudaGetSymbolAddress((void**)&wkl, g_wkl);
    cudaGetSymbolAddress((void**)&wvh, g_wvh); cudaGetSymbolAddress((void**)&wvl, g_wvl);
    cudaGetSymbolAddress((void**)&woh, g_woh); cudaGetSymbolAddress((void**)&wol, g_wol);

    cudaFuncSetAttribute(flash_mma,
                         cudaFuncAttributeMaxDynamicSharedMemorySize, FA_SMEM_BYTES);
    cudaFuncSetAttribute(gemm_qkv,
                         cudaFuncAttributeMaxDynamicSharedMemorySize, G_SMEM_BYTES);
    cudaFuncSetAttribute(gemm_out,
                         cudaFuncAttributeMaxDynamicSharedMemorySize, G_SMEM_BYTES);

    const int NX4 = SEQ * DMODEL / 4;
    const int NW4 = DMODEL * DMODEL / 4;

    split_kernel<<<NX4 / 256, 256>>>(x, xh, xl, NX4, 1.0f);
    split4_kernel<<<dim3(NW4 / 256, 4), 256>>>(
        W_Q, W_K, W_V, W_O,
        wqh, wql, wkh, wkl, wvh, wvl, woh, wol, NW4);

    gemm_qkv<<<dim3(SEQ / 128, DMODEL / 128, 3), 256, G_SMEM_BYTES>>>(
        xh, xl, wqh, wql, wkh, wkl, wvh, wvl,
        qh, ql, kh, vth);

    flash_mma<<<dim3(SEQ / 128, NHEAD), 256, FA_SMEM_BYTES>>>(
        qh, ql, kh, vth, zh, zl);

    gemm_out<<<dim3(SEQ / 128, DMODEL / 128), 256, G_SMEM_BYTES>>>(zh, zl, woh, wol, out);
}

// round 16
// speedup vs baseline: 1.4398x; 1.1918x over previous
#include <cuda_runtime.h>
#include <cuda_bf16.h>
#include <cuda_fp16.h>
#include <cstdint>
#include <math.h>

#define SEQ    4096
#define DMODEL 1024
#define NHEAD  16
#define DHEAD  64

typedef __nv_bfloat16 bf16;   // storage type; all payloads are fp16 bits now

__device__ __forceinline__ uint32_t smem_u32(const void* p) {
    uint32_t a;
    asm("{ .reg .u64 t; cvta.to.shared.u64 t, %1; cvt.u32.u64 %0, t; }" : "=r"(a) : "l"(p));
    return a;
}
__device__ __forceinline__ void ldsm_x4(uint32_t* r, uint32_t addr) {
    asm volatile("ldmatrix.sync.aligned.m8n8.x4.shared.b16 {%0,%1,%2,%3}, [%4];"
        : "=r"(r[0]), "=r"(r[1]), "=r"(r[2]), "=r"(r[3]) : "r"(addr));
}
__device__ __forceinline__ void mma_f16(float* c, const uint32_t* a, const uint32_t* b) {
    asm volatile(
        "mma.sync.aligned.m16n8k16.row.col.f32.f16.f16.f32 "
        "{%0,%1,%2,%3}, {%4,%5,%6,%7}, {%8,%9}, {%0,%1,%2,%3};"
        : "+f"(c[0]), "+f"(c[1]), "+f"(c[2]), "+f"(c[3])
        : "r"(a[0]), "r"(a[1]), "r"(a[2]), "r"(a[3]), "r"(b[0]), "r"(b[1]));
}
__device__ __forceinline__ float ex2f(float x) {
    float y; asm("ex2.approx.f32 %0,%1;" : "=f"(y) : "f"(x)); return y;
}
__device__ __forceinline__ uint32_t packh2(float lo, float hi) {
    uint32_t d; asm("cvt.rn.f16x2.f32 %0,%1,%2;" : "=r"(d) : "f"(hi), "f"(lo)); return d;
}
__device__ __forceinline__ float f16rt(float x) {
    return __half2float(__float2half_rn(x));
}

#define CP_ASYNC16(dst, src) \
    asm volatile("cp.async.cg.shared.global [%0],[%1],16;" :: "r"(dst), "l"(src))
#define CP_COMMIT()  asm volatile("cp.async.commit_group;")
#define CP_WAIT(n)   asm volatile("cp.async.wait_group %0;" :: "n"(n))

#define TSCL 0.1803368801f   /* 0.125 * log2(e), folded into W_Q */

// ========================= scratch (__device__ globals) =====================
// All fp16 bits. Activations (x, z) are hi/lo split pairs; weights single.
__device__ bf16 g_qh[(size_t)NHEAD * SEQ * DHEAD], g_ql[(size_t)NHEAD * SEQ * DHEAD];
__device__ bf16 g_kh[(size_t)NHEAD * SEQ * DHEAD];
__device__ bf16 g_vth[(size_t)NHEAD * SEQ * DHEAD];
__device__ bf16 g_zh[(size_t)SEQ * DMODEL], g_zl[(size_t)SEQ * DMODEL];
__device__ bf16 g_xh[(size_t)SEQ * DMODEL], g_xl[(size_t)SEQ * DMODEL];
__device__ bf16 g_wq[DMODEL * DMODEL], g_wk[DMODEL * DMODEL];
__device__ bf16 g_wv[DMODEL * DMODEL], g_wo[DMODEL * DMODEL];

// ============================ split kernels =================================
// x -> fp16 hi/lo split pair
__global__ __launch_bounds__(256) void split_x(
    const float* __restrict__ in, bf16* __restrict__ hi,
    bf16* __restrict__ lo, int n4)
{
    int i = blockIdx.x * 256 + threadIdx.x;
    if (i >= n4) return;
    float4 v = ((const float4*)in)[i];
    uint32_t* H = (uint32_t*)hi;
    uint32_t* L = (uint32_t*)lo;
    H[2 * i]     = packh2(v.x, v.y);
    H[2 * i + 1] = packh2(v.z, v.w);
    L[2 * i]     = packh2(v.x - f16rt(v.x), v.y - f16rt(v.y));
    L[2 * i + 1] = packh2(v.z - f16rt(v.z), v.w - f16rt(v.w));
}

// 4 weights -> single fp16 each in one launch; y selects {WQ(TSCL), WK, WV, WO}
__global__ __launch_bounds__(256) void split4_w(
    const float* __restrict__ w0, const float* __restrict__ w1,
    const float* __restrict__ w2, const float* __restrict__ w3,
    bf16* __restrict__ o0, bf16* __restrict__ o1,
    bf16* __restrict__ o2, bf16* __restrict__ o3, int n4)
{
    int i = blockIdx.x * 256 + threadIdx.x;
    if (i >= n4) return;
    const int z = blockIdx.y;
    const float* in = (z == 0) ? w0 : (z == 1) ? w1 : (z == 2) ? w2 : w3;
    bf16* out = (z == 0) ? o0 : (z == 1) ? o1 : (z == 2) ? o2 : o3;
    const float scale = (z == 0) ? TSCL : 1.0f;
    float4 v = ((const float4*)in)[i];
    v.x *= scale; v.y *= scale; v.z *= scale; v.w *= scale;
    uint32_t* O = (uint32_t*)out;
    O[2 * i]     = packh2(v.x, v.y);
    O[2 * i + 1] = packh2(v.z, v.w);
}

// == shared GEMM mainloop (fp16 asymmetric 2-term, 3-stage cp.async, 1 sync) ==
#define GSTR 40
#define ABYTES (128 * GSTR * 2)     // one A (or B) stage buffer in bytes
#define NITER 64                    // 2 terms x 32 K-chunks
#define G_SMEM_BYTES (6 * ABYTES)   // 3 stages x (A + B) = 61440

__device__ __forceinline__ void gemm_issue(
    uint32_t s0, const bf16* const* Aps, const bf16* __restrict__ B,
    int n, int m0, int n0, int crow0, int crow1, int ccol)
{
    const int b3 = n % 3;
    const uint32_t ao = s0 + b3 * ABYTES;
    const uint32_t bo = s0 + 3 * ABYTES + b3 * ABYTES;
    const bf16* Ap = Aps[n >> 5];
    const int k0 = (n & 31) * 32;
    CP_ASYNC16(ao + (crow0 * GSTR + ccol) * 2, Ap + (size_t)(m0 + crow0) * DMODEL + k0 + ccol);
    CP_ASYNC16(ao + (crow1 * GSTR + ccol) * 2, Ap + (size_t)(m0 + crow1) * DMODEL + k0 + ccol);
    CP_ASYNC16(bo + (crow0 * GSTR + ccol) * 2, B + (size_t)(n0 + crow0) * DMODEL + k0 + ccol);
    CP_ASYNC16(bo + (crow1 * GSTR + ccol) * 2, B + (size_t)(n0 + crow1) * DMODEL + k0 + ccol);
    CP_COMMIT();
}

__device__ __forceinline__ void gemm_core(
    const bf16* __restrict__ Ah, const bf16* __restrict__ Al,
    const bf16* __restrict__ B,
    int m0, int n0, bf16* sm, float acc[2][8][4])
{
    const int tid  = threadIdx.x;
    const int warp = tid >> 5, lane = tid & 31;
    const int wm = (warp & 3) * 32;
    const int wn = (warp >> 2) * 64;

    const uint32_t s0 = smem_u32(sm);
    const uint32_t a_addr0 = s0 + ((wm + (lane & 15)) * GSTR + (lane >> 4) * 8) * 2;
    const uint32_t b_addr0 = s0 + 3 * ABYTES +
        ((wn + (lane & 7) + ((lane >> 4) * 8)) * GSTR + (((lane >> 3) & 1) * 8)) * 2;

    const int crow0 = tid >> 2, ccol = (tid & 3) * 8;
    const int crow1 = (tid + 256) >> 2;

    const bf16* Aps[2];
    Aps[0] = Ah; Aps[1] = Al;

#pragma unroll
    for (int i = 0; i < 2; ++i)
#pragma unroll
        for (int j = 0; j < 8; ++j)
#pragma unroll
            for (int t = 0; t < 4; ++t) acc[i][j][t] = 0.0f;

    gemm_issue(s0, Aps, B, 0, m0, n0, crow0, crow1, ccol);
    gemm_issue(s0, Aps, B, 1, m0, n0, crow0, crow1, ccol);

#pragma unroll 1
    for (int c = 0; c < NITER; ++c) {
        if (c + 1 < NITER) { CP_WAIT(1); } else { CP_WAIT(0); }
        __syncthreads();
        if (c + 2 < NITER)
            gemm_issue(s0, Aps, B, c + 2, m0, n0, crow0, crow1, ccol);

        const uint32_t abuf = (c % 3) * ABYTES;
#pragma unroll
        for (int kk = 0; kk < 2; ++kk) {
            uint32_t a[2][4], b[8][2];
#pragma unroll
            for (int mt = 0; mt < 2; ++mt)
                ldsm_x4(a[mt], a_addr0 + abuf + (mt * 16 * GSTR + kk * 16) * 2);
#pragma unroll
            for (int j = 0; j < 4; ++j) {
                uint32_t r[4];
                ldsm_x4(r, b_addr0 + abuf + (j * 16 * GSTR + kk * 16) * 2);
                b[j * 2][0] = r[0]; b[j * 2][1] = r[1];
                b[j * 2 + 1][0] = r[2]; b[j * 2 + 1][1] = r[3];
            }
#pragma unroll
            for (int mt = 0; mt < 2; ++mt)
#pragma unroll
                for (int nt = 0; nt < 8; ++nt)
                    mma_f16(acc[mt][nt], a[mt], b[nt]);
        }
    }
}

// ---- fused QKV projection: z selects {Q->fp16 split, K->fp16, V->fp16 T} ----
__global__ __launch_bounds__(256) void gemm_qkv(
    const bf16* __restrict__ xh, const bf16* __restrict__ xl,
    const bf16* __restrict__ wq, const bf16* __restrict__ wk,
    const bf16* __restrict__ wv,
    bf16* __restrict__ qh, bf16* __restrict__ ql,
    bf16* __restrict__ kh, bf16* __restrict__ vth)
{
    extern __shared__ bf16 gsm[];
    const int sel = blockIdx.z;
    const bf16* B = (sel == 0) ? wq : (sel == 1) ? wk : wv;

    const int m0 = blockIdx.x * 128;
    const int n0 = blockIdx.y * 128;
    float acc[2][8][4];
    gemm_core(xh, xl, B, m0, n0, gsm, acc);

    const int warp = threadIdx.x >> 5, lane = threadIdx.x & 31;
    const int wm = (warp & 3) * 32, wn = (warp >> 2) * 64;
#pragma unroll
    for (int mt = 0; mt < 2; ++mt) {
#pragma unroll
        for (int nt = 0; nt < 8; ++nt) {
            int m = m0 + wm + mt * 16 + (lane >> 2);
            int n = n0 + wn + nt * 8 + 2 * (lane & 3);
            float c0 = acc[mt][nt][0], c1 = acc[mt][nt][1];
            float c2 = acc[mt][nt][2], c3 = acc[mt][nt][3];
            if (sel == 0) {          // Q: fp16 split pair
                size_t i0 = ((size_t)(n >> 6) * SEQ + m) * 64 + (n & 63);
                *(uint32_t*)(qh + i0) = packh2(c0, c1);
                *(uint32_t*)(ql + i0) = packh2(c0 - f16rt(c0), c1 - f16rt(c1));
                *(uint32_t*)(qh + i0 + 8 * 64) = packh2(c2, c3);
                *(uint32_t*)(ql + i0 + 8 * 64) = packh2(c2 - f16rt(c2), c3 - f16rt(c3));
            } else if (sel == 1) {   // K: single fp16
                size_t i0 = ((size_t)(n >> 6) * SEQ + m) * 64 + (n & 63);
                *(uint32_t*)(kh + i0) = packh2(c0, c1);
                *(uint32_t*)(kh + i0 + 8 * 64) = packh2(c2, c3);
            } else {                 // V: single fp16, transposed [H][64][S]
                size_t b0 = ((size_t)(n >> 6) * 64 + (n & 63)) * SEQ;
                *(__half*)(vth + b0 + m)           = __float2half_rn(c0);
                *(__half*)(vth + b0 + m + 8)       = __float2half_rn(c2);
                *(__half*)(vth + b0 + SEQ + m)     = __float2half_rn(c1);
                *(__half*)(vth + b0 + SEQ + m + 8) = __float2half_rn(c3);
            }
        }
    }
}

// ---- output projection (fp32 C, fp16 asymmetric) ----
__global__ __launch_bounds__(256) void gemm_out(
    const bf16* __restrict__ Ah, const bf16* __restrict__ Al,
    const bf16* __restrict__ B, float* __restrict__ C)
{
    extern __shared__ bf16 gsm[];
    const int m0 = blockIdx.x * 128;
    const int n0 = blockIdx.y * 128;
    float acc[2][8][4];
    gemm_core(Ah, Al, B, m0, n0, gsm, acc);

    const int warp = threadIdx.x >> 5, lane = threadIdx.x & 31;
    const int wm = (warp & 3) * 32, wn = (warp >> 2) * 64;
#pragma unroll
    for (int mt = 0; mt < 2; ++mt) {
#pragma unroll
        for (int nt = 0; nt < 8; ++nt) {
            int m = m0 + wm + mt * 16 + (lane >> 2);
            int n = n0 + wn + nt * 8 + 2 * (lane & 3);
            *(float2*)(C + (size_t)m * DMODEL + n) =
                make_float2(acc[mt][nt][0], acc[mt][nt][1]);
            *(float2*)(C + (size_t)(m + 8) * DMODEL + n) =
                make_float2(acc[mt][nt][2], acc[mt][nt][3]);
        }
    }
}

// ======== flash attention: fp16 asymmetric (q/p split, k/v single) ==========
// CTA: 128 q-rows x 1 head, 8 warps. K-blocks of 64. Q pre-scaled by TSCL.
// Smem: qh 128x72 | ql 128x72 | 2 stages x {k 64x72, vt 64x72}  (fp16 bits)
#define FSTR 72
#define SQL  (128 * FSTR)
#define SKV  (2 * 128 * FSTR)
#define STG  (2 * 64 * FSTR)
#define OV   (64 * FSTR)
#define FA_SMEM_BYTES ((SKV + 2 * STG) * 2)   // 73728

__global__ __launch_bounds__(256, 1) void flash_mma(
    const bf16* __restrict__ Qh, const bf16* __restrict__ Ql,
    const bf16* __restrict__ Kh, const bf16* __restrict__ Vth,
    bf16* __restrict__ Zh, bf16* __restrict__ Zl)
{
    extern __shared__ bf16 sm[];
    const uint32_t sbase = smem_u32(sm);
    const int tid = threadIdx.x;
    const int warp = tid >> 5, lane = tid & 31;
    const int wm = warp * 16;
    const int h  = blockIdx.y;
    const int iq = gridDim.x - 1 - blockIdx.x;   // big work first

    const int c_row = tid >> 3, c_c8 = tid & 7;
    const size_t kvh = (size_t)h * SEQ * 64;
    const int nblk = 2 * iq + 2;

    // prologue: stage 0 KV
    {
        const uint32_t dst = sbase + SKV * 2;
        const size_t ks = kvh + (size_t)c_row * 64 + c_c8 * 8;
        const size_t vs = ((size_t)h * 64 + c_row) * SEQ + c_c8 * 8;
#pragma unroll
        for (int it = 0; it < 2; ++it) {
            int row = c_row + it * 32;
            uint32_t d = dst + (row * FSTR + c_c8 * 8) * 2;
            CP_ASYNC16(d,           Kh  + ks + (size_t)it * 32 * 64);
            CP_ASYNC16(d + OV * 2,  Vth + vs + (size_t)it * 32 * SEQ);
        }
        CP_COMMIT();
    }

    // Q tiles (fp16 hi & lo)
    {
        const size_t qoff = ((size_t)h * SEQ + iq * 128) * 64;
#pragma unroll
        for (int it = 0; it < 4; ++it) {
            int idx = tid + it * 256;
            int row = idx >> 3, c8 = idx & 7;
            *(uint4*)(sm + row * FSTR + c8 * 8) =
                *(const uint4*)(Qh + qoff + (size_t)row * 64 + c8 * 8);
            *(uint4*)(sm + SQL + row * FSTR + c8 * 8) =
                *(const uint4*)(Ql + qoff + (size_t)row * 64 + c8 * 8);
        }
    }
    __syncthreads();

    uint32_t qfh[4][4], qfl[4][4];
    {
        const uint32_t aq = sbase + ((wm + (lane & 15)) * FSTR + (lane >> 4) * 8) * 2;
#pragma unroll
        for (int kt = 0; kt < 4; ++kt) {
            ldsm_x4(qfh[kt], aq + kt * 32);
            ldsm_x4(qfl[kt], aq + SQL * 2 + kt * 32);
        }
    }
    __syncthreads();

    float m0 = -1.0e30f, m1 = -1.0e30f, l0 = 0.0f, l1 = 0.0f;
    float oa[8][4];
#pragma unroll
    for (int j = 0; j < 8; ++j)
#pragma unroll
        for (int t = 0; t < 4; ++t) oa[j][t] = 0.0f;

#pragma unroll 1
    for (int jk = 0; jk < nblk; ++jk) {
        const int st = jk & 1;
        if (jk + 1 < nblk) {
            const int jn = jk + 1;
            const uint32_t dst = sbase + (SKV + (jn & 1) * STG) * 2;
            const size_t ks = kvh + ((size_t)jn * 64 + c_row) * 64 + c_c8 * 8;
            const size_t vs = ((size_t)h * 64 + c_row) * SEQ + jn * 64 + c_c8 * 8;
#pragma unroll
            for (int it = 0; it < 2; ++it) {
                int row = c_row + it * 32;
                uint32_t d = dst + (row * FSTR + c_c8 * 8) * 2;
                CP_ASYNC16(d,           Kh  + ks + (size_t)it * 32 * 64);
                CP_ASYNC16(d + OV * 2,  Vth + vs + (size_t)it * 32 * SEQ);
            }
            CP_COMMIT();
            CP_WAIT(1);
        } else {
            CP_WAIT(0);
        }
        __syncthreads();

        const uint32_t kbase = sbase + (SKV + st * STG) * 2;
        const uint32_t brow = (lane & 7) + ((lane >> 4) * 8);
        const uint32_t bcol = ((lane >> 3) & 1) * 8;

        // S = Q K^T : qh*k + ql*k  (fp16, q pre-scaled)
        float sa[8][4];
#pragma unroll
        for (int j = 0; j < 8; ++j)
#pragma unroll
            for (int t = 0; t < 4; ++t) sa[j][t] = 0.0f;

#pragma unroll
        for (int j = 0; j < 4; ++j) {
            const uint32_t rb = kbase + ((j * 16 + brow) * FSTR + bcol) * 2;
#pragma unroll
            for (int kt = 0; kt < 4; ++kt) {
                uint32_t bh[4];
                ldsm_x4(bh, rb + kt * 32);
                mma_f16(sa[2 * j],     qfh[kt], bh);
                mma_f16(sa[2 * j + 1], qfh[kt], bh + 2);
                mma_f16(sa[2 * j],     qfl[kt], bh);
                mma_f16(sa[2 * j + 1], qfl[kt], bh + 2);
            }
        }

        // causal mask (diagonal 128x128 region only)
        if (jk >= 2 * iq) {
            const int r0 = iq * 128 + wm + (lane >> 2);
#pragma unroll
            for (int nt = 0; nt < 8; ++nt)
#pragma unroll
                for (int cc = 0; cc < 4; ++cc) {
                    int col = jk * 64 + nt * 8 + 2 * (lane & 3) + (cc & 1);
                    int row = r0 + ((cc >= 2) ? 8 : 0);
                    if (col > row) sa[nt][cc] = -1.0e30f;
                }
        }

        // online softmax
        float pm0 = -1.0e30f, pm1 = -1.0e30f;
#pragma unroll
        for (int nt = 0; nt < 8; ++nt) {
            pm0 = fmaxf(pm0, fmaxf(sa[nt][0], sa[nt][1]));
            pm1 = fmaxf(pm1, fmaxf(sa[nt][2], sa[nt][3]));
        }
        pm0 = fmaxf(pm0, __shfl_xor_sync(0xffffffffu, pm0, 1));
        pm0 = fmaxf(pm0, __shfl_xor_sync(0xffffffffu, pm0, 2));
        pm1 = fmaxf(pm1, __shfl_xor_sync(0xffffffffu, pm1, 1));
        pm1 = fmaxf(pm1, __shfl_xor_sync(0xffffffffu, pm1, 2));

        float mn0 = fmaxf(m0, pm0), mn1 = fmaxf(m1, pm1);
        float al0 = ex2f(m0 - mn0), al1 = ex2f(m1 - mn1);
        m0 = mn0; m1 = mn1;

        float rs0 = 0.0f, rs1 = 0.0f;
#pragma unroll
        for (int nt = 0; nt < 8; ++nt) {
            float p0 = ex2f(sa[nt][0] - m0);
            float p1 = ex2f(sa[nt][1] - m0);
            float p2 = ex2f(sa[nt][2] - m1);
            float p3 = ex2f(sa[nt][3] - m1);
            sa[nt][0] = p0; sa[nt][1] = p1; sa[nt][2] = p2; sa[nt][3] = p3;
            rs0 += p0 + p1; rs1 += p2 + p3;
        }
        rs0 += __shfl_xor_sync(0xffffffffu, rs0, 1);
        rs0 += __shfl_xor_sync(0xffffffffu, rs0, 2);
        rs1 += __shfl_xor_sync(0xffffffffu, rs1, 1);
        rs1 += __shfl_xor_sync(0xffffffffu, rs1, 2);
        l0 = l0 * al0 + rs0;
        l1 = l1 * al1 + rs1;
#pragma unroll
        for (int nt = 0; nt < 8; ++nt) {
            oa[nt][0] *= al0; oa[nt][1] *= al0;
            oa[nt][2] *= al1; oa[nt][3] *= al1;
        }

        // O += P V : ph*v + pl*v  (fp16 P split, single fp16 V)
#pragma unroll
        for (int kt = 0; kt < 4; ++kt) {
            uint32_t pfh[4], pfl[4];
            {
                float a0 = sa[2 * kt][0], a1 = sa[2 * kt][1];
                float a2 = sa[2 * kt][2], a3 = sa[2 * kt][3];
                float b0 = sa[2 * kt + 1][0], b1 = sa[2 * kt + 1][1];
                float b2 = sa[2 * kt + 1][2], b3 = sa[2 * kt + 1][3];
                pfh[0] = packh2(a0, a1);  pfh[1] = packh2(a2, a3);
                pfh[2] = packh2(b0, b1);  pfh[3] = packh2(b2, b3);
                pfl[0] = packh2(a0 - f16rt(a0), a1 - f16rt(a1));
                pfl[1] = packh2(a2 - f16rt(a2), a3 - f16rt(a3));
                pfl[2] = packh2(b0 - f16rt(b0), b1 - f16rt(b1));
                pfl[3] = packh2(b2 - f16rt(b2), b3 - f16rt(b3));
            }
#pragma unroll
            for (int j = 0; j < 4; ++j) {
                const uint32_t vb = kbase + (OV + (j * 16 + brow) * FSTR + bcol) * 2 + kt * 32;
                uint32_t vh[4];
                ldsm_x4(vh, vb);
                mma_f16(oa[2 * j],     pfh, vh);
                mma_f16(oa[2 * j + 1], pfh, vh + 2);
                mma_f16(oa[2 * j],     pfl, vh);
                mma_f16(oa[2 * j + 1], pfl, vh + 2);
            }
        }
        __syncthreads();
    }

    // epilogue: normalize + write zh/zl fp16 splits
    const float inv0 = 1.0f / l0, inv1 = 1.0f / l1;
    const int s0 = iq * 128 + wm + (lane >> 2);
    const size_t b0 = (size_t)s0 * DMODEL + h * 64;
    const size_t b1 = b0 + 8 * DMODEL;
#pragma unroll
    for (int nt = 0; nt < 8; ++nt) {
        int e = nt * 8 + 2 * (lane & 3);
        float a0 = oa[nt][0] * inv0, a1 = oa[nt][1] * inv0;
        float a2 = oa[nt][2] * inv1, a3 = oa[nt][3] * inv1;
        *(uint32_t*)(Zh + b0 + e) = packh2(a0, a1);
        *(uint32_t*)(Zl + b0 + e) = packh2(a0 - f16rt(a0), a1 - f16rt(a1));
        *(uint32_t*)(Zh + b1 + e) = packh2(a2, a3);
        *(uint32_t*)(Zl + b1 + e) = packh2(a2 - f16rt(a2), a3 - f16rt(a3));
    }
}

// ---------------------------------------------------------------------------
extern "C" void kernel_launch(void* const* d_in, const int* in_sizes, int n_in,
                              void* d_out, int out_size)
{
    const float* x   = (const float*)d_in[0];
    const float* W_K = (const float*)d_in[1];
    const float* W_Q = (const float*)d_in[2];
    const float* W_V = (const float*)d_in[3];
    const float* W_O = (const float*)d_in[4];
    float* out = (float*)d_out;

    bf16 *qh, *ql, *kh, *vth, *zh, *zl, *xh, *xl, *wq, *wk, *wv, *wo;
    cudaGetSymbolAddress((void**)&qh, g_qh);   cudaGetSymbolAddress((void**)&ql, g_ql);
    cudaGetSymbolAddress((void**)&kh, g_kh);
    cudaGetSymbolAddress((void**)&vth, g_vth);
    cudaGetSymbolAddress((void**)&zh, g_zh);   cudaGetSymbolAddress((void**)&zl, g_zl);
    cudaGetSymbolAddress((void**)&xh, g_xh);   cudaGetSymbolAddress((void**)&xl, g_xl);
    cudaGetSymbolAddress((void**)&wq, g_wq);   cudaGetSymbolAddress((void**)&wk, g_wk);
    cudaGetSymbolAddress((void**)&wv, g_wv);   cudaGetSymbolAddress((void**)&wo, g_wo);

    cudaFuncSetAttribute(flash_mma,
                         cudaFuncAttributeMaxDynamicSharedMemorySize, FA_SMEM_BYTES);
    cudaFuncSetAttribute(gemm_qkv,
                         cudaFuncAttributeMaxDynamicSharedMemorySize, G_SMEM_BYTES);
    cudaFuncSetAttribute(gemm_out,
                         cudaFuncAttributeMaxDynamicSharedMemorySize, G_SMEM_BYTES);

    const int NX4 = SEQ * DMODEL / 4;
    const int NW4 = DMODEL * DMODEL / 4;

    split_x<<<NX4 / 256, 256>>>(x, xh, xl, NX4);
    split4_w<<<dim3(NW4 / 256, 4), 256>>>(W_Q, W_K, W_V, W_O, wq, wk, wv, wo, NW4);

    gemm_qkv<<<dim3(SEQ / 128, DMODEL / 128, 3), 256, G_SMEM_BYTES>>>(
        xh, xl, wq, wk, wv, qh, ql, kh, vth);

    flash_mma<<<dim3(SEQ / 128, NHEAD), 256, FA_SMEM_BYTES>>>(
        qh, ql, kh, vth, zh, zl);

    gemm_out<<<dim3(SEQ / 128, DMODEL / 128), 256, G_SMEM_BYTES>>>(zh, zl, wo, out);
}